// round 8
// baseline (speedup 1.0000x reference)
#include <cuda_runtime.h>
#include <cstdint>
#include <cstddef>

#define EDIM 1024
#define NHEAD 16
#define HDIM 64
#define FFDIM 4096
#define BATCH 4
#define SEQ 2048
#define NTOK (BATCH*SEQ)   // 8192

// ------------------- scratch (device globals; no allocations) -------------------
__device__ float g_qlnr[(size_t)NTOK*EDIM];   // LN1(q) tf32-rounded (GEMM A)
__device__ float g_qln [(size_t)NTOK*EDIM];   // LN1(q) raw (residual)
__device__ float g_vln[(size_t)NTOK*EDIM];
__device__ float g_kln[(size_t)NTOK*EDIM];
__device__ float g_Q  [(size_t)NTOK*EDIM];
__device__ float g_K  [(size_t)NTOK*EDIM];
__device__ float g_V  [(size_t)NTOK*EDIM];
__device__ float g_att[(size_t)NTOK*EDIM];
__device__ float g_x  [(size_t)NTOK*EDIM];
__device__ float g_h  [(size_t)NTOK*EDIM];
__device__ float g_ff [(size_t)NTOK*FFDIM];
__device__ float g_maskf[(size_t)BATCH*SEQ];
__device__ float g_Wq[(size_t)EDIM*EDIM];
__device__ float g_Wk[(size_t)EDIM*EDIM];
__device__ float g_Wv[(size_t)EDIM*EDIM];
__device__ float g_Wo[(size_t)EDIM*EDIM];
__device__ float g_W1[(size_t)EDIM*FFDIM];
__device__ float g_W2[(size_t)FFDIM*EDIM];

// ------------------- helpers -------------------
__device__ __forceinline__ uint32_t f2tf(float f) {
    uint32_t u;
    asm("cvt.rna.tf32.f32 %0, %1;" : "=r"(u) : "f"(f));
    return u;
}
__device__ __forceinline__ float f2tf_f(float f) { return __uint_as_float(f2tf(f)); }

__device__ __forceinline__ void mma8(float* c, const uint32_t* a, const uint32_t* b) {
    asm volatile(
        "mma.sync.aligned.m16n8k8.row.col.f32.tf32.tf32.f32 "
        "{%0,%1,%2,%3},{%4,%5,%6,%7},{%8,%9},{%0,%1,%2,%3};\n"
        : "+f"(c[0]), "+f"(c[1]), "+f"(c[2]), "+f"(c[3])
        : "r"(a[0]), "r"(a[1]), "r"(a[2]), "r"(a[3]), "r"(b[0]), "r"(b[1]));
}

__device__ __forceinline__ float gelu_exact(float v) {
    return 0.5f * v * (1.0f + erff(v * 0.70710678118654752f));
}

#define CP16(dst_sm, src_g) \
    asm volatile("cp.async.cg.shared.global [%0], [%1], 16;\n" :: \
        "r"((uint32_t)__cvta_generic_to_shared(dst_sm)), "l"(src_g))
#define CP_COMMIT() asm volatile("cp.async.commit_group;\n")
#define CP_WAIT1()  asm volatile("cp.async.wait_group 1;\n")
#define CP_WAIT0()  asm volatile("cp.async.wait_group 0;\n")

// ------------------- mask -> float addend -------------------
__global__ __launch_bounds__(256) void maskf_kernel(
    const int* __restrict__ mask, float* __restrict__ mf)
{
    int i = blockIdx.x * 256 + threadIdx.x;
    mf[i] = (mask[i] == 0) ? -1e20f : 0.0f;
}

// ------------------- tf32 pre-round (weights) -------------------
__global__ __launch_bounds__(256) void round_kernel(
    const float* __restrict__ in, float* __restrict__ out)
{
    int i = (blockIdx.x * 256 + threadIdx.x) * 4;
    float4 v = *reinterpret_cast<const float4*>(in + i);
    float4 o;
    o.x = f2tf_f(v.x); o.y = f2tf_f(v.y); o.z = f2tf_f(v.z); o.w = f2tf_f(v.w);
    *reinterpret_cast<float4*>(out + i) = o;
}

// ------------------- LayerNorm (rounded out; optional raw out2) -------------------
__global__ __launch_bounds__(256) void ln_kernel(
    const float* __restrict__ in, float* __restrict__ out, float* __restrict__ out2,
    const float* __restrict__ gw, const float* __restrict__ gb)
{
    int row = blockIdx.x;
    int tid = threadIdx.x;
    const float4* inr = reinterpret_cast<const float4*>(in + (size_t)row * EDIM);
    float4 v = inr[tid];
    float s  = v.x + v.y + v.z + v.w;
    float sq = v.x*v.x + v.y*v.y + v.z*v.z + v.w*v.w;

    int lane = tid & 31, warp = tid >> 5;
    #pragma unroll
    for (int o = 16; o > 0; o >>= 1) {
        s  += __shfl_xor_sync(0xffffffffu, s, o);
        sq += __shfl_xor_sync(0xffffffffu, sq, o);
    }
    __shared__ float rs[8], rq[8];
    if (lane == 0) { rs[warp] = s; rq[warp] = sq; }
    __syncthreads();
    if (warp == 0) {
        float s2 = (lane < 8) ? rs[lane] : 0.0f;
        float q2 = (lane < 8) ? rq[lane] : 0.0f;
        #pragma unroll
        for (int o = 4; o > 0; o >>= 1) {
            s2 += __shfl_xor_sync(0xffffffffu, s2, o);
            q2 += __shfl_xor_sync(0xffffffffu, q2, o);
        }
        if (lane == 0) { rs[0] = s2; rq[0] = q2; }
    }
    __syncthreads();
    float mean = rs[0] * (1.0f / EDIM);
    float var  = rq[0] * (1.0f / EDIM) - mean * mean;
    float rstd = rsqrtf(var + 1e-5f);

    float4 gg = reinterpret_cast<const float4*>(gw)[tid];
    float4 bb = reinterpret_cast<const float4*>(gb)[tid];
    float4 o4;
    o4.x = (v.x - mean) * rstd * gg.x + bb.x;
    o4.y = (v.y - mean) * rstd * gg.y + bb.y;
    o4.z = (v.z - mean) * rstd * gg.z + bb.z;
    o4.w = (v.w - mean) * rstd * gg.w + bb.w;
    if (out2) reinterpret_cast<float4*>(out2 + (size_t)row * EDIM)[tid] = o4;
    float4 r4;
    r4.x = f2tf_f(o4.x); r4.y = f2tf_f(o4.y); r4.z = f2tf_f(o4.z); r4.w = f2tf_f(o4.w);
    reinterpret_cast<float4*>(out + (size_t)row * EDIM)[tid] = r4;
}

// ------------------- flash attention v2 (register softmax, no mainloop cvt) -------------------
// Inputs Q/K/V are tf32-pre-rounded. grid (16,16,4), 256 thr, 2 CTAs/SM.
#define FLASH_SMEM_WORDS 26624

__global__ __launch_bounds__(256, 2) void flash_kernel(
    const float* __restrict__ Qg, const float* __restrict__ Kg,
    const float* __restrict__ Vg, const float* __restrict__ maskf,
    float* __restrict__ Og)
{
    extern __shared__ float sm[];
    float*    Qs = sm;
    float*    Ks = sm + 8704;
    float*    Vs = sm + 17408;
    uint32_t* Qsu = (uint32_t*)Qs;
    uint32_t* Ksu = (uint32_t*)Ks;
    uint32_t* Vsu = (uint32_t*)Vs;

    int qt = blockIdx.x, h = blockIdx.y, b = blockIdx.z;
    int tokbase = b * SEQ + qt * 128;
    const float* Qb  = Qg + (size_t)tokbase * EDIM + h * HDIM;
    const float* Kb0 = Kg + (size_t)b * SEQ * EDIM + h * HDIM;
    const float* Vb0 = Vg + (size_t)b * SEQ * EDIM + h * HDIM;
    const float* mfb = maskf + (size_t)b * SEQ;

    int tid = threadIdx.x, w = tid >> 5, lane = tid & 31;
    int g = lane >> 2, t4 = lane & 3;
    int r0 = w * 16 + g;
    int lo = lane & ~3;

    #pragma unroll
    for (int it = 0; it < 8; it++) {
        int idx = tid + it * 256;
        int r = idx >> 4, c4 = (idx & 15) * 4;
        float4 v = *reinterpret_cast<const float4*>(Qb + (size_t)r * EDIM + c4);
        float4 pk;
        pk.x = v.x * 0.125f; pk.y = v.y * 0.125f;
        pk.z = v.z * 0.125f; pk.w = v.w * 0.125f;
        *reinterpret_cast<float4*>(&Qs[r * 68 + c4]) = pk;
    }

    auto issue_kv = [&](int j, int buf) {
        const float* Kc = Kb0 + (size_t)j * 64 * EDIM;
        const float* Vc = Vb0 + (size_t)j * 64 * EDIM;
        float* Kd = Ks + buf * 4352;
        float* Vd = Vs + buf * 4608;
        #pragma unroll
        for (int it = 0; it < 4; it++) {
            int idx = tid + it * 256;
            int r = idx >> 4, c4 = (idx & 15) * 4;
            CP16(&Kd[r * 68 + c4], Kc + (size_t)r * EDIM + c4);
        }
        #pragma unroll
        for (int it = 0; it < 4; it++) {
            int idx = tid + it * 256;
            int r = idx >> 4, c4 = (idx & 15) * 4;
            CP16(&Vd[r * 72 + c4], Vc + (size_t)r * EDIM + c4);
        }
    };

    issue_kv(0, 0);
    CP_COMMIT();

    float m0 = -1e30f, m1 = -1e30f, l0 = 0.0f, l1 = 0.0f;
    float oacc[8][4];
    #pragma unroll
    for (int nf = 0; nf < 8; nf++)
        #pragma unroll
        for (int i = 0; i < 4; i++) oacc[nf][i] = 0.0f;

    const int NCH = SEQ / 64;
    for (int j = 0; j < NCH; j++) {
        int buf = j & 1;
        if (j + 1 < NCH) { issue_kv(j + 1, buf ^ 1); CP_COMMIT(); CP_WAIT1(); }
        else             { CP_WAIT0(); }
        __syncthreads();

        const uint32_t* Kb = Ksu + buf * 4352;
        const uint32_t* Vb = Vsu + buf * 4608;

        float sacc[8][4];
        #pragma unroll
        for (int nf = 0; nf < 8; nf++)
            #pragma unroll
            for (int i = 0; i < 4; i++) sacc[nf][i] = 0.0f;

        #pragma unroll
        for (int kk = 0; kk < 8; kk++) {
            uint32_t afr[4];
            afr[0] = Qsu[r0 * 68 + kk * 8 + t4];
            afr[1] = Qsu[(r0 + 8) * 68 + kk * 8 + t4];
            afr[2] = Qsu[r0 * 68 + kk * 8 + t4 + 4];
            afr[3] = Qsu[(r0 + 8) * 68 + kk * 8 + t4 + 4];
            uint32_t bfr[8][2];
            #pragma unroll
            for (int nf = 0; nf < 8; nf++) {
                int n = nf * 8 + g;
                bfr[nf][0] = Kb[n * 68 + kk * 8 + t4];
                bfr[nf][1] = Kb[n * 68 + kk * 8 + t4 + 4];
            }
            #pragma unroll
            for (int nf = 0; nf < 8; nf++)
                mma8(sacc[nf], afr, bfr[nf]);
        }

        const float2* mf2 = (const float2*)(mfb + j * 64);
        float mx0 = -1e30f, mx1 = -1e30f;
        #pragma unroll
        for (int nf = 0; nf < 8; nf++) {
            float2 md = mf2[nf * 4 + t4];
            sacc[nf][0] += md.x; sacc[nf][1] += md.y;
            sacc[nf][2] += md.x; sacc[nf][3] += md.y;
            mx0 = fmaxf(mx0, fmaxf(sacc[nf][0], sacc[nf][1]));
            mx1 = fmaxf(mx1, fmaxf(sacc[nf][2], sacc[nf][3]));
        }
        mx0 = fmaxf(mx0, __shfl_xor_sync(0xffffffffu, mx0, 1));
        mx0 = fmaxf(mx0, __shfl_xor_sync(0xffffffffu, mx0, 2));
        mx1 = fmaxf(mx1, __shfl_xor_sync(0xffffffffu, mx1, 1));
        mx1 = fmaxf(mx1, __shfl_xor_sync(0xffffffffu, mx1, 2));
        float mn0 = fmaxf(m0, mx0), mn1 = fmaxf(m1, mx1);
        float c0 = __expf(m0 - mn0), c1 = __expf(m1 - mn1);
        float s0 = 0.0f, s1 = 0.0f;
        #pragma unroll
        for (int nf = 0; nf < 8; nf++) {
            float p00 = __expf(sacc[nf][0] - mn0);
            float p01 = __expf(sacc[nf][1] - mn0);
            float p10 = __expf(sacc[nf][2] - mn1);
            float p11 = __expf(sacc[nf][3] - mn1);
            s0 += p00 + p01; s1 += p10 + p11;
            sacc[nf][0] = __uint_as_float(f2tf(p00));
            sacc[nf][1] = __uint_as_float(f2tf(p01));
            sacc[nf][2] = __uint_as_float(f2tf(p10));
            sacc[nf][3] = __uint_as_float(f2tf(p11));
        }
        s0 += __shfl_xor_sync(0xffffffffu, s0, 1);
        s0 += __shfl_xor_sync(0xffffffffu, s0, 2);
        s1 += __shfl_xor_sync(0xffffffffu, s1, 1);
        s1 += __shfl_xor_sync(0xffffffffu, s1, 2);
        l0 = l0 * c0 + s0; l1 = l1 * c1 + s1;
        m0 = mn0; m1 = mn1;

        #pragma unroll
        for (int nf = 0; nf < 8; nf++) {
            oacc[nf][0] *= c0; oacc[nf][1] *= c0;
            oacc[nf][2] *= c1; oacc[nf][3] *= c1;
        }
        #pragma unroll
        for (int kk = 0; kk < 8; kk++) {
            float q00 = __shfl_sync(0xffffffffu, sacc[kk][0], lo + (t4 >> 1));
            float q01 = __shfl_sync(0xffffffffu, sacc[kk][1], lo + (t4 >> 1));
            float q10 = __shfl_sync(0xffffffffu, sacc[kk][2], lo + (t4 >> 1));
            float q11 = __shfl_sync(0xffffffffu, sacc[kk][3], lo + (t4 >> 1));
            float q20 = __shfl_sync(0xffffffffu, sacc[kk][0], lo + 2 + (t4 >> 1));
            float q21 = __shfl_sync(0xffffffffu, sacc[kk][1], lo + 2 + (t4 >> 1));
            float q30 = __shfl_sync(0xffffffffu, sacc[kk][2], lo + 2 + (t4 >> 1));
            float q31 = __shfl_sync(0xffffffffu, sacc[kk][3], lo + 2 + (t4 >> 1));
            bool odd = (t4 & 1);
            uint32_t afr[4];
            afr[0] = __float_as_uint(odd ? q01 : q00);
            afr[1] = __float_as_uint(odd ? q11 : q10);
            afr[2] = __float_as_uint(odd ? q21 : q20);
            afr[3] = __float_as_uint(odd ? q31 : q30);
            uint32_t bfr[8][2];
            #pragma unroll
            for (int nf = 0; nf < 8; nf++) {
                int n = nf * 8 + g;
                bfr[nf][0] = Vb[(kk * 8 + t4) * 72 + n];
                bfr[nf][1] = Vb[(kk * 8 + t4 + 4) * 72 + n];
            }
            #pragma unroll
            for (int nf = 0; nf < 8; nf++)
                mma8(oacc[nf], afr, bfr[nf]);
        }
        __syncthreads();
    }

    float inv0 = 1.0f / l0, inv1 = 1.0f / l1;
    float* Ob = Og + (size_t)tokbase * EDIM + h * HDIM;
    #pragma unroll
    for (int nf = 0; nf < 8; nf++) {
        int c = nf * 8 + 2 * t4;
        float2 o0, o1;
        o0.x = f2tf_f(oacc[nf][0] * inv0); o0.y = f2tf_f(oacc[nf][1] * inv0);
        o1.x = f2tf_f(oacc[nf][2] * inv1); o1.y = f2tf_f(oacc[nf][3] * inv1);
        *reinterpret_cast<float2*>(Ob + (size_t)r0 * EDIM + c)       = o0;
        *reinterpret_cast<float2*>(Ob + (size_t)(r0 + 8) * EDIM + c) = o1;
    }
}

// ------------------- NN tf32 GEMM: CTA 128x256, warp 64x64, 3-stage cp.async -------------------
// Inputs pre-rounded to tf32 -> fragments load raw (no cvt).
// EPI: 0 none, 2 +bias+res, 3 gelu(acc+bias). RND: round output to tf32.
// smem: As 3 x 128x36, Bs 3 x 32x264 (stride 264 -> B-frag bank (8*t4+g)%32 bijective)
#define GEMM_SMEM_WORDS (3*4608 + 3*8448)

template<int EPI, int RND>
__global__ __launch_bounds__(256) void gemm_nn(
    const float* __restrict__ A, const float* __restrict__ Bm, float* __restrict__ C,
    int K, int N,
    const float* __restrict__ bias, const float* __restrict__ res)
{
    extern __shared__ float smf[];
    float* As = smf;
    float* Bs = smf + 3 * 4608;
    uint32_t* Asu = (uint32_t*)As;
    uint32_t* Bsu = (uint32_t*)Bs;

    int m0 = blockIdx.y * 128, n0 = blockIdx.x * 256;
    int tid = threadIdx.x, warp = tid >> 5, lane = tid & 31;
    int wm = (warp >> 2) * 64, wn = (warp & 3) * 64;   // 2 x 4 warp grid, 64x64 tile
    int g = lane >> 2, t4 = lane & 3;

    const int T = K >> 5;

    auto issue = [&](int t) {
        int s = t % 3;
        int k0 = t << 5;
        float* Ad = As + s * 4608;
        float* Bd = Bs + s * 8448;
        #pragma unroll
        for (int it = 0; it < 4; it++) {
            int idx = tid + it * 256;
            int r = idx >> 3, c4 = (idx & 7) * 4;
            CP16(&Ad[r * 36 + c4], A + (size_t)(m0 + r) * K + k0 + c4);
        }
        #pragma unroll
        for (int it = 0; it < 8; it++) {
            int idx = tid + it * 256;
            int r = idx >> 6, c4 = (idx & 63) * 4;
            CP16(&Bd[r * 264 + c4], Bm + (size_t)(k0 + r) * N + n0 + c4);
        }
    };

    float acc[4][8][4];
    #pragma unroll
    for (int a = 0; a < 4; a++)
        #pragma unroll
        for (int c = 0; c < 8; c++)
            #pragma unroll
            for (int i = 0; i < 4; i++) acc[a][c][i] = 0.0f;

    issue(0);
    CP_COMMIT();

    for (int t = 0; t < T; t++) {
        if (t + 1 < T) { issue(t + 1); CP_COMMIT(); CP_WAIT1(); }
        else           { CP_WAIT0(); }
        __syncthreads();

        const uint32_t* Af = Asu + (t % 3) * 4608;
        const uint32_t* Bf = Bsu + (t % 3) * 8448;
        #pragma unroll
        for (int kk = 0; kk < 32; kk += 8) {
            uint32_t afr[4][4], bfr[8][2];
            #pragma unroll
            for (int mf = 0; mf < 4; mf++) {
                int mr = wm + mf * 16 + g;
                afr[mf][0] = Af[mr * 36 + kk + t4];
                afr[mf][1] = Af[(mr + 8) * 36 + kk + t4];
                afr[mf][2] = Af[mr * 36 + kk + t4 + 4];
                afr[mf][3] = Af[(mr + 8) * 36 + kk + t4 + 4];
            }
            #pragma unroll
            for (int nf = 0; nf < 8; nf++) {
                int n = wn + nf * 8 + g;
                bfr[nf][0] = Bf[(kk + t4) * 264 + n];
                bfr[nf][1] = Bf[(kk + t4 + 4) * 264 + n];
            }
            #pragma unroll
            for (int mf = 0; mf < 4; mf++)
                #pragma unroll
                for (int nf = 0; nf < 8; nf++)
                    mma8(acc[mf][nf], afr[mf], bfr[nf]);
        }
    }

    // vectorized epilogue: acc[..][0,1] adjacent cols; [2,3] same at m+8
    #pragma unroll
    for (int mf = 0; mf < 4; mf++) {
        #pragma unroll
        for (int nf = 0; nf < 8; nf++) {
            int m = m0 + wm + mf * 16 + g;
            int n = n0 + wn + nf * 8 + 2 * t4;
            float2 v0 = make_float2(acc[mf][nf][0], acc[mf][nf][1]);
            float2 v1 = make_float2(acc[mf][nf][2], acc[mf][nf][3]);
            if (EPI >= 1) {
                float2 bz = *reinterpret_cast<const float2*>(bias + n);
                v0.x += bz.x; v0.y += bz.y;
                v1.x += bz.x; v1.y += bz.y;
            }
            if (EPI == 2) {
                float2 r0 = *reinterpret_cast<const float2*>(res + (size_t)m * N + n);
                float2 r1 = *reinterpret_cast<const float2*>(res + (size_t)(m + 8) * N + n);
                v0.x += r0.x; v0.y += r0.y;
                v1.x += r1.x; v1.y += r1.y;
            }
            if (EPI == 3) {
                v0.x = gelu_exact(v0.x); v0.y = gelu_exact(v0.y);
                v1.x = gelu_exact(v1.x); v1.y = gelu_exact(v1.y);
            }
            if (RND) {
                v0.x = f2tf_f(v0.x); v0.y = f2tf_f(v0.y);
                v1.x = f2tf_f(v1.x); v1.y = f2tf_f(v1.y);
            }
            *reinterpret_cast<float2*>(C + (size_t)m * N + n)       = v0;
            *reinterpret_cast<float2*>(C + (size_t)(m + 8) * N + n) = v1;
        }
    }
}

// ------------------- host launch -------------------
static float* sym_addr(const void* symbol) {
    void* p = nullptr;
    cudaGetSymbolAddress(&p, symbol);
    return reinterpret_cast<float*>(p);
}

extern "C" void kernel_launch(void* const* d_in, const int* in_sizes, int n_in,
                              void* d_out, int out_size) {
    (void)in_sizes; (void)n_in; (void)out_size;
    const float* value = (const float*)d_in[0];
    const float* key   = (const float*)d_in[1];
    const float* query = (const float*)d_in[2];
    const int*   mask  = (const int*)  d_in[3];
    const float* Wv    = (const float*)d_in[4];
    const float* Wk    = (const float*)d_in[5];
    const float* Wq    = (const float*)d_in[6];
    const float* Wo    = (const float*)d_in[7];
    const float* bo    = (const float*)d_in[8];
    const float* ln1_g = (const float*)d_in[9];
    const float* ln1_b = (const float*)d_in[10];
    const float* ln2_g = (const float*)d_in[11];
    const float* ln2_b = (const float*)d_in[12];
    const float* lnf_g = (const float*)d_in[13];
    const float* lnf_b = (const float*)d_in[14];
    const float* W1    = (const float*)d_in[15];
    const float* b1    = (const float*)d_in[16];
    const float* W2    = (const float*)d_in[17];
    const float* b2    = (const float*)d_in[18];
    float* out = (float*)d_out;

    float* p_qlnr = sym_addr(g_qlnr);
    float* p_qln = sym_addr(g_qln);
    float* p_vln = sym_addr(g_vln);
    float* p_kln = sym_addr(g_kln);
    float* p_Q   = sym_addr(g_Q);
    float* p_K   = sym_addr(g_K);
    float* p_V   = sym_addr(g_V);
    float* p_att = sym_addr(g_att);
    float* p_x   = sym_addr(g_x);
    float* p_h   = sym_addr(g_h);
    float* p_ff  = sym_addr(g_ff);
    float* p_mf  = sym_addr(g_maskf);
    float* p_Wq  = sym_addr(g_Wq);
    float* p_Wk  = sym_addr(g_Wk);
    float* p_Wv  = sym_addr(g_Wv);
    float* p_Wo  = sym_addr(g_Wo);
    float* p_W1  = sym_addr(g_W1);
    float* p_W2  = sym_addr(g_W2);

    const int GSM = GEMM_SMEM_WORDS * 4;     // 156672
    const int FSM = FLASH_SMEM_WORDS * 4;    // 106496
    cudaFuncSetAttribute(gemm_nn<0,1>, cudaFuncAttributeMaxDynamicSharedMemorySize, GSM);
    cudaFuncSetAttribute(gemm_nn<2,0>, cudaFuncAttributeMaxDynamicSharedMemorySize, GSM);
    cudaFuncSetAttribute(gemm_nn<3,1>, cudaFuncAttributeMaxDynamicSharedMemorySize, GSM);
    cudaFuncSetAttribute(flash_kernel, cudaFuncAttributeMaxDynamicSharedMemorySize, FSM);

    // 0) mask addends + weight pre-round
    maskf_kernel<<<NTOK / 256, 256>>>(mask, p_mf);
    round_kernel<<<EDIM*EDIM/1024, 256>>>(Wq, p_Wq);
    round_kernel<<<EDIM*EDIM/1024, 256>>>(Wk, p_Wk);
    round_kernel<<<EDIM*EDIM/1024, 256>>>(Wv, p_Wv);
    round_kernel<<<EDIM*EDIM/1024, 256>>>(Wo, p_Wo);
    round_kernel<<<EDIM*FFDIM/1024, 256>>>(W1, p_W1);
    round_kernel<<<EDIM*FFDIM/1024, 256>>>(W2, p_W2);

    // 1) pre-norms (rounded outputs; raw copy of LN1(q) for residual)
    ln_kernel<<<NTOK, 256>>>(query, p_qlnr, p_qln, ln1_g, ln1_b);
    ln_kernel<<<NTOK, 256>>>(value, p_vln, nullptr, ln2_g, ln2_b);
    ln_kernel<<<NTOK, 256>>>(key,   p_kln, nullptr, ln2_g, ln2_b);

    // 2) QKV projections (rounded outputs)
    dim3 gProj(EDIM / 256, NTOK / 128, 1);
    gemm_nn<0,1><<<gProj, 256, GSM>>>(p_qlnr, p_Wq, p_Q, EDIM, EDIM, nullptr, nullptr);
    gemm_nn<0,1><<<gProj, 256, GSM>>>(p_kln, p_Wk, p_K, EDIM, EDIM, nullptr, nullptr);
    gemm_nn<0,1><<<gProj, 256, GSM>>>(p_vln, p_Wv, p_V, EDIM, EDIM, nullptr, nullptr);

    // 3) fused attention (rounded output)
    dim3 gF(SEQ / 128, NHEAD, BATCH);
    flash_kernel<<<gF, 256, FSM>>>(p_Q, p_K, p_V, p_mf, p_att);

    // 4) x = att @ Wo + bo + LN1(q)_raw   (unrounded)
    gemm_nn<2,0><<<gProj, 256, GSM>>>(p_att, p_Wo, p_x, EDIM, EDIM, bo, p_qln);

    // 5) h = LN_f(x) (rounded)
    ln_kernel<<<NTOK, 256>>>(p_x, p_h, nullptr, lnf_g, lnf_b);

    // 6) ff = gelu(h @ W1 + b1) (rounded)
    dim3 gF1(FFDIM / 256, NTOK / 128, 1);
    gemm_nn<3,1><<<gF1, 256, GSM>>>(p_h, p_W1, p_ff, EDIM, FFDIM, b1, nullptr);

    // 7) out = ff @ W2 + b2 + x (unrounded)
    dim3 gF2(EDIM / 256, NTOK / 128, 1);
    gemm_nn<2,0><<<gF2, 256, GSM>>>(p_ff, p_W2, out, FFDIM, EDIM, b2, p_x);
}

// round 10
// speedup vs baseline: 2.7733x; 2.7733x over previous
#include <cuda_runtime.h>
#include <cuda_fp16.h>
#include <cstdint>
#include <cstddef>

#define EDIM 1024
#define NHEAD 16
#define HDIM 64
#define FFDIM 4096
#define BATCH 4
#define SEQ 2048
#define NTOK (BATCH*SEQ)   // 8192

// ------------------- scratch (device globals; no allocations) -------------------
__device__ __half   g_qln_h[(size_t)NTOK*EDIM];
__device__ float    g_qln  [(size_t)NTOK*EDIM];   // raw fp32 residual
__device__ __half   g_vln_h[(size_t)NTOK*EDIM];
__device__ __half   g_kln_h[(size_t)NTOK*EDIM];
__device__ __half   g_Q [(size_t)NTOK*EDIM];
__device__ __half   g_K [(size_t)NTOK*EDIM];
__device__ __half   g_V [(size_t)NTOK*EDIM];
__device__ uint32_t g_Vp[(size_t)NTOK/2*EDIM];    // token-pair packed V
__device__ __half   g_att[(size_t)NTOK*EDIM];
__device__ float    g_x [(size_t)NTOK*EDIM];
__device__ __half   g_hh[(size_t)NTOK*EDIM];
__device__ __half   g_ff[(size_t)NTOK*FFDIM];
__device__ float    g_maskf[(size_t)BATCH*SEQ];
__device__ uint32_t g_Wq[(size_t)EDIM/2*EDIM];    // k-pair packed weights
__device__ uint32_t g_Wk[(size_t)EDIM/2*EDIM];
__device__ uint32_t g_Wv[(size_t)EDIM/2*EDIM];
__device__ uint32_t g_Wo[(size_t)EDIM/2*EDIM];
__device__ uint32_t g_W1[(size_t)EDIM/2*FFDIM];
__device__ uint32_t g_W2[(size_t)FFDIM/2*EDIM];

// ------------------- helpers -------------------
__device__ __forceinline__ uint32_t pack2(float lo, float hi) {
    __half2 h = __floats2half2_rn(lo, hi);
    return *reinterpret_cast<uint32_t*>(&h);
}

__device__ __forceinline__ void mma16(float* c, const uint32_t* a, const uint32_t* b) {
    asm volatile(
        "mma.sync.aligned.m16n8k16.row.col.f32.f16.f16.f32 "
        "{%0,%1,%2,%3},{%4,%5,%6,%7},{%8,%9},{%0,%1,%2,%3};\n"
        : "+f"(c[0]), "+f"(c[1]), "+f"(c[2]), "+f"(c[3])
        : "r"(a[0]), "r"(a[1]), "r"(a[2]), "r"(a[3]), "r"(b[0]), "r"(b[1]));
}

__device__ __forceinline__ float gelu_exact(float v) {
    return 0.5f * v * (1.0f + erff(v * 0.70710678118654752f));
}

#define CP16(dst_sm, src_g) \
    asm volatile("cp.async.cg.shared.global [%0], [%1], 16;\n" :: \
        "r"((uint32_t)__cvta_generic_to_shared(dst_sm)), "l"(src_g))
#define CP_COMMIT() asm volatile("cp.async.commit_group;\n")
#define CP_WAIT1()  asm volatile("cp.async.wait_group 1;\n")
#define CP_WAIT0()  asm volatile("cp.async.wait_group 0;\n")

// ------------------- mask -> float addend -------------------
__global__ __launch_bounds__(256) void maskf_kernel(
    const int* __restrict__ mask, float* __restrict__ mf)
{
    int i = blockIdx.x * 256 + threadIdx.x;
    mf[i] = (mask[i] == 0) ? -1e20f : 0.0f;
}

// ------------------- weight pack: fp32 [K][N] -> half2-k-pair words [K/2][N] ---
__global__ __launch_bounds__(256) void wpack_kernel(
    const float* __restrict__ W, uint32_t* __restrict__ Wp, int N)
{
    int gid = blockIdx.x * 256 + threadIdx.x;
    int qpr = N >> 2;
    int p = gid / qpr, n = (gid % qpr) * 4;
    float4 r0 = *reinterpret_cast<const float4*>(W + (size_t)(2 * p) * N + n);
    float4 r1 = *reinterpret_cast<const float4*>(W + (size_t)(2 * p + 1) * N + n);
    uint4 o;
    o.x = pack2(r0.x, r1.x); o.y = pack2(r0.y, r1.y);
    o.z = pack2(r0.z, r1.z); o.w = pack2(r0.w, r1.w);
    *reinterpret_cast<uint4*>(Wp + (size_t)p * N + n) = o;
}

// ------------------- V pack: half [NTOK][E] -> token-pair words [NTOK/2][E] ----
__global__ __launch_bounds__(256) void vpack_kernel(
    const uint32_t* __restrict__ Vh, uint32_t* __restrict__ Vp)
{
    int gid = blockIdx.x * 256 + threadIdx.x;
    int pg = gid >> 8;
    int n = (gid & 255) * 4;
    uint2 a = *reinterpret_cast<const uint2*>(Vh + (size_t)(2 * pg) * 512 + (n >> 1));
    uint2 b = *reinterpret_cast<const uint2*>(Vh + (size_t)(2 * pg + 1) * 512 + (n >> 1));
    uint4 o;
    o.x = (a.x & 0xFFFFu) | (b.x << 16);
    o.y = (a.x >> 16)     | (b.x & 0xFFFF0000u);
    o.z = (a.y & 0xFFFFu) | (b.y << 16);
    o.w = (a.y >> 16)     | (b.y & 0xFFFF0000u);
    *reinterpret_cast<uint4*>(Vp + (size_t)pg * 1024 + n) = o;
}

// ------------------- LayerNorm (half out; optional raw fp32 out2) -------------------
__global__ __launch_bounds__(256) void ln_kernel(
    const float* __restrict__ in, uint32_t* __restrict__ outh, float* __restrict__ out2,
    const float* __restrict__ gw, const float* __restrict__ gb)
{
    int row = blockIdx.x;
    int tid = threadIdx.x;
    const float4* inr = reinterpret_cast<const float4*>(in + (size_t)row * EDIM);
    float4 v = inr[tid];
    float s  = v.x + v.y + v.z + v.w;
    float sq = v.x*v.x + v.y*v.y + v.z*v.z + v.w*v.w;

    int lane = tid & 31, warp = tid >> 5;
    #pragma unroll
    for (int o = 16; o > 0; o >>= 1) {
        s  += __shfl_xor_sync(0xffffffffu, s, o);
        sq += __shfl_xor_sync(0xffffffffu, sq, o);
    }
    __shared__ float rs[8], rq[8];
    if (lane == 0) { rs[warp] = s; rq[warp] = sq; }
    __syncthreads();
    if (warp == 0) {
        float s2 = (lane < 8) ? rs[lane] : 0.0f;
        float q2 = (lane < 8) ? rq[lane] : 0.0f;
        #pragma unroll
        for (int o = 4; o > 0; o >>= 1) {
            s2 += __shfl_xor_sync(0xffffffffu, s2, o);
            q2 += __shfl_xor_sync(0xffffffffu, q2, o);
        }
        if (lane == 0) { rs[0] = s2; rq[0] = q2; }
    }
    __syncthreads();
    float mean = rs[0] * (1.0f / EDIM);
    float var  = rq[0] * (1.0f / EDIM) - mean * mean;
    float rstd = rsqrtf(var + 1e-5f);

    float4 gg = reinterpret_cast<const float4*>(gw)[tid];
    float4 bb = reinterpret_cast<const float4*>(gb)[tid];
    float4 o4;
    o4.x = (v.x - mean) * rstd * gg.x + bb.x;
    o4.y = (v.y - mean) * rstd * gg.y + bb.y;
    o4.z = (v.z - mean) * rstd * gg.z + bb.z;
    o4.w = (v.w - mean) * rstd * gg.w + bb.w;
    if (out2) reinterpret_cast<float4*>(out2 + (size_t)row * EDIM)[tid] = o4;
    uint2 w2;
    w2.x = pack2(o4.x, o4.y);
    w2.y = pack2(o4.z, o4.w);
    reinterpret_cast<uint2*>(outh + (size_t)row * 512)[tid] = w2;
}

// ------------------- flash attention fp16 (register softmax, zero shuffles) ---
// grid (16,16,4), 256 thr, 2 CTAs/SM. Warp tile 16 q-rows x 64 kv.
// smem words: Qs [0,4608) 128x36 (half2 along dim, Q*0.125);
//             Ks [4608,9216) 2 x 64x36; Vs [9216,13824) 2 x 32x72 (token-pairs).
#define FLASH_SMEM_WORDS 13824

__global__ __launch_bounds__(256, 2) void flash_kernel(
    const __half* __restrict__ Qg, const __half* __restrict__ Kg,
    const uint32_t* __restrict__ Vp, const float* __restrict__ maskf,
    uint32_t* __restrict__ Og)
{
    extern __shared__ uint32_t smu[];
    uint32_t* Qs = smu;
    uint32_t* Ks = smu + 4608;
    uint32_t* Vs = smu + 9216;

    int qt = blockIdx.x, h = blockIdx.y, b = blockIdx.z;
    int tokbase = b * SEQ + qt * 128;
    const uint32_t* Qw  = (const uint32_t*)Qg + (size_t)tokbase * 512 + h * 32;
    const __half*   Kb0 = Kg + (size_t)b * SEQ * EDIM + h * HDIM;
    const uint32_t* Vp0 = Vp + (size_t)(b * SEQ / 2) * EDIM + h * HDIM;
    const float*    mfb = maskf + (size_t)b * SEQ;

    int tid = threadIdx.x, w = tid >> 5, lane = tid & 31;
    int g = lane >> 2, t4 = lane & 3;
    int r0 = w * 16 + g;

    // stage Q (scale by 0.125, exact in half)
    __half2 sc = __float2half2_rn(0.125f);
    #pragma unroll
    for (int it = 0; it < 8; it++) {
        int idx = tid + it * 256;
        int r = idx >> 4, c = (idx & 15) * 2;
        uint2 v = *reinterpret_cast<const uint2*>(Qw + (size_t)r * 512 + c);
        __half2 h0 = __hmul2(*reinterpret_cast<__half2*>(&v.x), sc);
        __half2 h1 = __hmul2(*reinterpret_cast<__half2*>(&v.y), sc);
        uint2 o;
        o.x = *reinterpret_cast<uint32_t*>(&h0);
        o.y = *reinterpret_cast<uint32_t*>(&h1);
        *reinterpret_cast<uint2*>(&Qs[r * 36 + c]) = o;
    }

    auto issue_kv = [&](int j, int buf) {
        const __half* Kc = Kb0 + (size_t)j * 64 * EDIM;
        const uint32_t* Vc = Vp0 + (size_t)(j * 32) * EDIM;
        uint32_t* Kd = Ks + buf * 2304;
        uint32_t* Vd = Vs + buf * 2304;
        #pragma unroll
        for (int it = 0; it < 2; it++) {
            int idx = tid + it * 256;
            int r = idx >> 3, c = idx & 7;
            CP16(&Kd[r * 36 + c * 4], Kc + (size_t)r * EDIM + c * 8);
        }
        #pragma unroll
        for (int it = 0; it < 2; it++) {
            int idx = tid + it * 256;
            int p = idx >> 4, c = idx & 15;
            CP16(&Vd[p * 72 + c * 4], Vc + (size_t)p * EDIM + c * 4);
        }
    };

    issue_kv(0, 0);
    CP_COMMIT();

    float m0 = -1e30f, m1 = -1e30f, l0 = 0.0f, l1 = 0.0f;
    float oacc[8][4];
    #pragma unroll
    for (int nf = 0; nf < 8; nf++)
        #pragma unroll
        for (int i = 0; i < 4; i++) oacc[nf][i] = 0.0f;

    const int NCH = SEQ / 64;
    for (int j = 0; j < NCH; j++) {
        int buf = j & 1;
        if (j + 1 < NCH) { issue_kv(j + 1, buf ^ 1); CP_COMMIT(); CP_WAIT1(); }
        else             { CP_WAIT0(); }
        __syncthreads();

        const uint32_t* Kb = Ks + buf * 2304;
        const uint32_t* Vb = Vs + buf * 2304;

        // ---- S = (Q*0.125) @ K^T ----
        float sacc[8][4];
        #pragma unroll
        for (int nf = 0; nf < 8; nf++)
            #pragma unroll
            for (int i = 0; i < 4; i++) sacc[nf][i] = 0.0f;

        #pragma unroll
        for (int s = 0; s < 4; s++) {
            uint32_t afr[4];
            afr[0] = Qs[r0 * 36 + 8 * s + t4];
            afr[1] = Qs[(r0 + 8) * 36 + 8 * s + t4];
            afr[2] = Qs[r0 * 36 + 8 * s + 4 + t4];
            afr[3] = Qs[(r0 + 8) * 36 + 8 * s + 4 + t4];
            uint32_t bfr[8][2];
            #pragma unroll
            for (int nf = 0; nf < 8; nf++) {
                int n = nf * 8 + g;
                bfr[nf][0] = Kb[n * 36 + 8 * s + t4];
                bfr[nf][1] = Kb[n * 36 + 8 * s + 4 + t4];
            }
            #pragma unroll
            for (int nf = 0; nf < 8; nf++)
                mma16(sacc[nf], afr, bfr[nf]);
        }

        // ---- mask + register softmax ----
        const float2* mf2 = (const float2*)(mfb + j * 64);
        float mx0 = -1e30f, mx1 = -1e30f;
        #pragma unroll
        for (int nf = 0; nf < 8; nf++) {
            float2 md = mf2[nf * 4 + t4];
            sacc[nf][0] += md.x; sacc[nf][1] += md.y;
            sacc[nf][2] += md.x; sacc[nf][3] += md.y;
            mx0 = fmaxf(mx0, fmaxf(sacc[nf][0], sacc[nf][1]));
            mx1 = fmaxf(mx1, fmaxf(sacc[nf][2], sacc[nf][3]));
        }
        mx0 = fmaxf(mx0, __shfl_xor_sync(0xffffffffu, mx0, 1));
        mx0 = fmaxf(mx0, __shfl_xor_sync(0xffffffffu, mx0, 2));
        mx1 = fmaxf(mx1, __shfl_xor_sync(0xffffffffu, mx1, 1));
        mx1 = fmaxf(mx1, __shfl_xor_sync(0xffffffffu, mx1, 2));
        float mn0 = fmaxf(m0, mx0), mn1 = fmaxf(m1, mx1);
        float c0 = __expf(m0 - mn0), c1 = __expf(m1 - mn1);
        float s0 = 0.0f, s1 = 0.0f;
        uint32_t ppk0[8], ppk1[8];
        #pragma unroll
        for (int nf = 0; nf < 8; nf++) {
            float p00 = __expf(sacc[nf][0] - mn0);
            float p01 = __expf(sacc[nf][1] - mn0);
            float p10 = __expf(sacc[nf][2] - mn1);
            float p11 = __expf(sacc[nf][3] - mn1);
            s0 += p00 + p01; s1 += p10 + p11;
            ppk0[nf] = pack2(p00, p01);
            ppk1[nf] = pack2(p10, p11);
        }
        s0 += __shfl_xor_sync(0xffffffffu, s0, 1);
        s0 += __shfl_xor_sync(0xffffffffu, s0, 2);
        s1 += __shfl_xor_sync(0xffffffffu, s1, 1);
        s1 += __shfl_xor_sync(0xffffffffu, s1, 2);
        l0 = l0 * c0 + s0; l1 = l1 * c1 + s1;
        m0 = mn0; m1 = mn1;

        // ---- rescale O, accumulate P @ V (A-fragment = ppk regs, no shuffles) ----
        #pragma unroll
        for (int nf = 0; nf < 8; nf++) {
            oacc[nf][0] *= c0; oacc[nf][1] *= c0;
            oacc[nf][2] *= c1; oacc[nf][3] *= c1;
        }
        #pragma unroll
        for (int s = 0; s < 4; s++) {
            uint32_t afr[4];
            afr[0] = ppk0[2 * s];
            afr[1] = ppk1[2 * s];
            afr[2] = ppk0[2 * s + 1];
            afr[3] = ppk1[2 * s + 1];
            uint32_t bfr[8][2];
            #pragma unroll
            for (int nf = 0; nf < 8; nf++) {
                int n = nf * 8 + g;
                bfr[nf][0] = Vb[(8 * s + t4) * 72 + n];
                bfr[nf][1] = Vb[(8 * s + 4 + t4) * 72 + n];
            }
            #pragma unroll
            for (int nf = 0; nf < 8; nf++)
                mma16(oacc[nf], afr, bfr[nf]);
        }
        __syncthreads();
    }

    float inv0 = 1.0f / l0, inv1 = 1.0f / l1;
    uint32_t* Ob = Og + (size_t)tokbase * 512 + h * 32;
    #pragma unroll
    for (int nf = 0; nf < 8; nf++) {
        int cw = nf * 4 + t4;
        Ob[(size_t)r0 * 512 + cw]       = pack2(oacc[nf][0] * inv0, oacc[nf][1] * inv0);
        Ob[(size_t)(r0 + 8) * 512 + cw] = pack2(oacc[nf][2] * inv1, oacc[nf][3] * inv1);
    }
}

// ------------------- fp16 NN GEMM: CTA 128x128, warp 64x32, BK=64, 3-stage ----
// A: half [M][K]; Bp: packed k-pairs [K/2][N] words.
// EPI: 0 none, 2 +bias+res, 3 gelu(acc+bias). OUTH: 1 -> half out, 0 -> fp32.
#define GEMM_SMEM_WORDS (3*4608 + 3*4352)

template<int EPI, int OUTH>
__global__ __launch_bounds__(256, 2) void gemm_h(
    const __half* __restrict__ A, const uint32_t* __restrict__ Bp, void* __restrict__ Cv,
    int K, int N, const float* __restrict__ bias, const float* __restrict__ res)
{
    extern __shared__ uint32_t smu[];
    uint32_t* As = smu;              // 3 x 128 x 36 (half2 words along k)
    uint32_t* Bs = smu + 3 * 4608;   // 3 x 32 x 136

    int m0 = blockIdx.y * 128, n0 = blockIdx.x * 128;
    int tid = threadIdx.x, warp = tid >> 5, lane = tid & 31;
    int wm = (warp >> 2) * 64, wn = (warp & 3) * 32;
    int g = lane >> 2, t4 = lane & 3;

    const int T = K >> 6;

    auto issue = [&](int t) {
        int s = t % 3;
        int k0 = t << 6;
        uint32_t* Ad = As + s * 4608;
        uint32_t* Bd = Bs + s * 4352;
        #pragma unroll
        for (int it = 0; it < 4; it++) {
            int idx = tid + it * 256;
            int r = idx >> 3, c = idx & 7;
            CP16(&Ad[r * 36 + c * 4], A + (size_t)(m0 + r) * K + k0 + c * 8);
        }
        int p0 = k0 >> 1;
        #pragma unroll
        for (int it = 0; it < 4; it++) {
            int idx = tid + it * 256;
            int p = idx >> 5, c = idx & 31;
            CP16(&Bd[p * 136 + c * 4], Bp + (size_t)(p0 + p) * N + n0 + c * 4);
        }
    };

    float acc[4][4][4];
    #pragma unroll
    for (int a = 0; a < 4; a++)
        #pragma unroll
        for (int c = 0; c < 4; c++)
            #pragma unroll
            for (int i = 0; i < 4; i++) acc[a][c][i] = 0.0f;

    issue(0);
    CP_COMMIT();

    for (int t = 0; t < T; t++) {
        if (t + 1 < T) { issue(t + 1); CP_COMMIT(); CP_WAIT1(); }
        else           { CP_WAIT0(); }
        __syncthreads();

        const uint32_t* Af = As + (t % 3) * 4608;
        const uint32_t* Bf = Bs + (t % 3) * 4352;
        #pragma unroll
        for (int s = 0; s < 4; s++) {     // 4 k16 steps per k64 tile
            uint32_t afr[4][4], bfr[4][2];
            #pragma unroll
            for (int mf = 0; mf < 4; mf++) {
                int r = wm + mf * 16 + g;
                afr[mf][0] = Af[r * 36 + 8 * s + t4];
                afr[mf][1] = Af[(r + 8) * 36 + 8 * s + t4];
                afr[mf][2] = Af[r * 36 + 8 * s + 4 + t4];
                afr[mf][3] = Af[(r + 8) * 36 + 8 * s + 4 + t4];
            }
            #pragma unroll
            for (int nf = 0; nf < 4; nf++) {
                int n = wn + nf * 8 + g;
                bfr[nf][0] = Bf[(8 * s + t4) * 136 + n];
                bfr[nf][1] = Bf[(8 * s + 4 + t4) * 136 + n];
            }
            #pragma unroll
            for (int mf = 0; mf < 4; mf++)
                #pragma unroll
                for (int nf = 0; nf < 4; nf++)
                    mma16(acc[mf][nf], afr[mf], bfr[nf]);
        }
    }

    #pragma unroll
    for (int mf = 0; mf < 4; mf++) {
        #pragma unroll
        for (int nf = 0; nf < 4; nf++) {
            int m = m0 + wm + mf * 16 + g;
            int n = n0 + wn + nf * 8 + 2 * t4;
            float2 v0 = make_float2(acc[mf][nf][0], acc[mf][nf][1]);
            float2 v1 = make_float2(acc[mf][nf][2], acc[mf][nf][3]);
            if (EPI >= 1) {
                float2 bz = *reinterpret_cast<const float2*>(bias + n);
                v0.x += bz.x; v0.y += bz.y;
                v1.x += bz.x; v1.y += bz.y;
            }
            if (EPI == 2) {
                float2 r0 = *reinterpret_cast<const float2*>(res + (size_t)m * N + n);
                float2 r1 = *reinterpret_cast<const float2*>(res + (size_t)(m + 8) * N + n);
                v0.x += r0.x; v0.y += r0.y;
                v1.x += r1.x; v1.y += r1.y;
            }
            if (EPI == 3) {
                v0.x = gelu_exact(v0.x); v0.y = gelu_exact(v0.y);
                v1.x = gelu_exact(v1.x); v1.y = gelu_exact(v1.y);
            }
            if (OUTH) {
                uint32_t* Ch = (uint32_t*)Cv;
                Ch[((size_t)m * N + n) >> 1]       = pack2(v0.x, v0.y);
                Ch[((size_t)(m + 8) * N + n) >> 1] = pack2(v1.x, v1.y);
            } else {
                float* Cf = (float*)Cv;
                *reinterpret_cast<float2*>(Cf + (size_t)m * N + n)       = v0;
                *reinterpret_cast<float2*>(Cf + (size_t)(m + 8) * N + n) = v1;
            }
        }
    }
}

// ------------------- host launch -------------------
static void* sym_addr(const void* symbol) {
    void* p = nullptr;
    cudaGetSymbolAddress(&p, symbol);
    return p;
}

extern "C" void kernel_launch(void* const* d_in, const int* in_sizes, int n_in,
                              void* d_out, int out_size) {
    (void)in_sizes; (void)n_in; (void)out_size;
    const float* value = (const float*)d_in[0];
    const float* key   = (const float*)d_in[1];
    const float* query = (const float*)d_in[2];
    const int*   mask  = (const int*)  d_in[3];
    const float* Wv    = (const float*)d_in[4];
    const float* Wk    = (const float*)d_in[5];
    const float* Wq    = (const float*)d_in[6];
    const float* Wo    = (const float*)d_in[7];
    const float* bo    = (const float*)d_in[8];
    const float* ln1_g = (const float*)d_in[9];
    const float* ln1_b = (const float*)d_in[10];
    const float* ln2_g = (const float*)d_in[11];
    const float* ln2_b = (const float*)d_in[12];
    const float* lnf_g = (const float*)d_in[13];
    const float* lnf_b = (const float*)d_in[14];
    const float* W1    = (const float*)d_in[15];
    const float* b1    = (const float*)d_in[16];
    const float* W2    = (const float*)d_in[17];
    const float* b2    = (const float*)d_in[18];
    float* out = (float*)d_out;

    __half*   p_qln_h = (__half*)sym_addr(g_qln_h);
    float*    p_qln   = (float*)sym_addr(g_qln);
    __half*   p_vln_h = (__half*)sym_addr(g_vln_h);
    __half*   p_kln_h = (__half*)sym_addr(g_kln_h);
    __half*   p_Q     = (__half*)sym_addr(g_Q);
    __half*   p_K     = (__half*)sym_addr(g_K);
    __half*   p_V     = (__half*)sym_addr(g_V);
    uint32_t* p_Vp    = (uint32_t*)sym_addr(g_Vp);
    __half*   p_att   = (__half*)sym_addr(g_att);
    float*    p_x     = (float*)sym_addr(g_x);
    __half*   p_hh    = (__half*)sym_addr(g_hh);
    __half*   p_ff    = (__half*)sym_addr(g_ff);
    float*    p_mf    = (float*)sym_addr(g_maskf);
    uint32_t* p_Wq    = (uint32_t*)sym_addr(g_Wq);
    uint32_t* p_Wk    = (uint32_t*)sym_addr(g_Wk);
    uint32_t* p_Wv    = (uint32_t*)sym_addr(g_Wv);
    uint32_t* p_Wo    = (uint32_t*)sym_addr(g_Wo);
    uint32_t* p_W1    = (uint32_t*)sym_addr(g_W1);
    uint32_t* p_W2    = (uint32_t*)sym_addr(g_W2);

    const int GSM = GEMM_SMEM_WORDS * 4;     // 107520
    const int FSM = FLASH_SMEM_WORDS * 4;    // 55296
    cudaFuncSetAttribute(gemm_h<0,1>, cudaFuncAttributeMaxDynamicSharedMemorySize, GSM);
    cudaFuncSetAttribute(gemm_h<2,0>, cudaFuncAttributeMaxDynamicSharedMemorySize, GSM);
    cudaFuncSetAttribute(gemm_h<3,1>, cudaFuncAttributeMaxDynamicSharedMemorySize, GSM);
    cudaFuncSetAttribute(flash_kernel, cudaFuncAttributeMaxDynamicSharedMemorySize, FSM);

    // 0) mask addends + weight packing
    maskf_kernel<<<NTOK / 256, 256>>>(mask, p_mf);
    wpack_kernel<<<EDIM*EDIM/8/256, 256>>>(Wq, p_Wq, EDIM);
    wpack_kernel<<<EDIM*EDIM/8/256, 256>>>(Wk, p_Wk, EDIM);
    wpack_kernel<<<EDIM*EDIM/8/256, 256>>>(Wv, p_Wv, EDIM);
    wpack_kernel<<<EDIM*EDIM/8/256, 256>>>(Wo, p_Wo, EDIM);
    wpack_kernel<<<EDIM*FFDIM/8/256, 256>>>(W1, p_W1, FFDIM);
    wpack_kernel<<<FFDIM*EDIM/8/256, 256>>>(W2, p_W2, EDIM);

    // 1) pre-norms (half outputs; raw fp32 LN1(q) for residual)
    ln_kernel<<<NTOK, 256>>>(query, (uint32_t*)p_qln_h, p_qln, ln1_g, ln1_b);
    ln_kernel<<<NTOK, 256>>>(value, (uint32_t*)p_vln_h, nullptr, ln2_g, ln2_b);
    ln_kernel<<<NTOK, 256>>>(key,   (uint32_t*)p_kln_h, nullptr, ln2_g, ln2_b);

    // 2) QKV projections (half out)
    dim3 gProj(EDIM / 128, NTOK / 128, 1);
    gemm_h<0,1><<<gProj, 256, GSM>>>(p_qln_h, p_Wq, p_Q, EDIM, EDIM, nullptr, nullptr);
    gemm_h<0,1><<<gProj, 256, GSM>>>(p_kln_h, p_Wk, p_K, EDIM, EDIM, nullptr, nullptr);
    gemm_h<0,1><<<gProj, 256, GSM>>>(p_vln_h, p_Wv, p_V, EDIM, EDIM, nullptr, nullptr);

    // 2b) pack V into token pairs for PV mma B-operand
    vpack_kernel<<<NTOK/2*EDIM/4/256, 256>>>((uint32_t*)p_V, p_Vp);

    // 3) fused attention (half out)
    dim3 gF(SEQ / 128, NHEAD, BATCH);
    flash_kernel<<<gF, 256, FSM>>>(p_Q, p_K, p_Vp, p_mf, (uint32_t*)p_att);

    // 4) x = att @ Wo + bo + LN1(q)_raw  (fp32 out)
    gemm_h<2,0><<<gProj, 256, GSM>>>(p_att, p_Wo, p_x, EDIM, EDIM, bo, p_qln);

    // 5) h = LN_f(x) (half out)
    ln_kernel<<<NTOK, 256>>>(p_x, (uint32_t*)p_hh, nullptr, lnf_g, lnf_b);

    // 6) ff = gelu(h @ W1 + b1) (half out)
    dim3 gF1(FFDIM / 128, NTOK / 128, 1);
    gemm_h<3,1><<<gF1, 256, GSM>>>(p_hh, p_W1, p_ff, EDIM, FFDIM, b1, nullptr);

    // 7) out = ff @ W2 + b2 + x (fp32 out)
    dim3 gF2(EDIM / 128, NTOK / 128, 1);
    gemm_h<2,0><<<gF2, 256, GSM>>>(p_ff, p_W2, out, FFDIM, EDIM, b2, p_x);
}

// round 11
// speedup vs baseline: 2.9156x; 1.0513x over previous
#include <cuda_runtime.h>
#include <cuda_fp16.h>
#include <cstdint>
#include <cstddef>

#define EDIM 1024
#define NHEAD 16
#define HDIM 64
#define FFDIM 4096
#define BATCH 4
#define SEQ 2048
#define NTOK (BATCH*SEQ)   // 8192

// ------------------- scratch (device globals; no allocations) -------------------
__device__ __half   g_qln_h[(size_t)NTOK*EDIM];
__device__ float    g_qln  [(size_t)NTOK*EDIM];   // raw fp32 residual
__device__ __half   g_vln_h[(size_t)NTOK*EDIM];
__device__ __half   g_kln_h[(size_t)NTOK*EDIM];
__device__ __half   g_Q [(size_t)NTOK*EDIM];
__device__ __half   g_K [(size_t)NTOK*EDIM];
__device__ __half   g_V [(size_t)NTOK*EDIM];
__device__ uint32_t g_Vp[(size_t)NTOK/2*EDIM];    // token-pair packed V
__device__ __half   g_att[(size_t)NTOK*EDIM];
__device__ float    g_x [(size_t)NTOK*EDIM];
__device__ __half   g_hh[(size_t)NTOK*EDIM];
__device__ __half   g_ff[(size_t)NTOK*FFDIM];
__device__ float    g_maskf[(size_t)BATCH*SEQ];
// weights packed TRANSPOSED: [N][K/2] half2-k-pair words
__device__ uint32_t g_Wq[(size_t)EDIM*EDIM/2];
__device__ uint32_t g_Wk[(size_t)EDIM*EDIM/2];
__device__ uint32_t g_Wv[(size_t)EDIM*EDIM/2];
__device__ uint32_t g_Wo[(size_t)EDIM*EDIM/2];
__device__ uint32_t g_W1[(size_t)FFDIM*EDIM/2];   // [4096][512]
__device__ uint32_t g_W2[(size_t)EDIM*FFDIM/2];   // [1024][2048]

// ------------------- helpers -------------------
__device__ __forceinline__ uint32_t pack2(float lo, float hi) {
    __half2 h = __floats2half2_rn(lo, hi);
    return *reinterpret_cast<uint32_t*>(&h);
}

__device__ __forceinline__ void mma16(float* c, const uint32_t* a, const uint32_t* b) {
    asm volatile(
        "mma.sync.aligned.m16n8k16.row.col.f32.f16.f16.f32 "
        "{%0,%1,%2,%3},{%4,%5,%6,%7},{%8,%9},{%0,%1,%2,%3};\n"
        : "+f"(c[0]), "+f"(c[1]), "+f"(c[2]), "+f"(c[3])
        : "r"(a[0]), "r"(a[1]), "r"(a[2]), "r"(a[3]), "r"(b[0]), "r"(b[1]));
}

#define LDSM4(R0,R1,R2,R3,ADDR) \
    asm volatile("ldmatrix.sync.aligned.m8n8.x4.shared.b16 {%0,%1,%2,%3}, [%4];\n" \
        : "=r"(R0), "=r"(R1), "=r"(R2), "=r"(R3) : "r"(ADDR))

__device__ __forceinline__ float gelu_exact(float v) {
    return 0.5f * v * (1.0f + erff(v * 0.70710678118654752f));
}

#define CP16(dst_sm, src_g) \
    asm volatile("cp.async.cg.shared.global [%0], [%1], 16;\n" :: \
        "r"((uint32_t)__cvta_generic_to_shared(dst_sm)), "l"(src_g))
#define CP_COMMIT() asm volatile("cp.async.commit_group;\n")
#define CP_WAIT1()  asm volatile("cp.async.wait_group 1;\n")
#define CP_WAIT0()  asm volatile("cp.async.wait_group 0;\n")

// ------------------- mask -> float addend -------------------
__global__ __launch_bounds__(256) void maskf_kernel(
    const int* __restrict__ mask, float* __restrict__ mf)
{
    int i = blockIdx.x * 256 + threadIdx.x;
    mf[i] = (mask[i] == 0) ? -1e20f : 0.0f;
}

// ---- weight pack+transpose: fp32 [K][N] -> words [N][K/2] (k-pair minor) ----
__global__ __launch_bounds__(256) void wpackT_kernel(
    const float* __restrict__ W, uint32_t* __restrict__ Wp, int K, int N)
{
    __shared__ float sm[64][33];
    int n0 = blockIdx.x * 32, k0 = blockIdx.y * 64;
    int tid = threadIdx.x;
    #pragma unroll
    for (int i = 0; i < 2; i++) {
        int idx = tid + i * 256;
        int r = idx >> 3, c4 = (idx & 7) * 4;
        float4 v = *reinterpret_cast<const float4*>(W + (size_t)(k0 + r) * N + n0 + c4);
        sm[r][c4] = v.x; sm[r][c4+1] = v.y; sm[r][c4+2] = v.z; sm[r][c4+3] = v.w;
    }
    __syncthreads();
    int rn = tid >> 3, wc = (tid & 7) * 4;
    uint4 o;
    o.x = pack2(sm[2*wc  ][rn], sm[2*wc+1][rn]);
    o.y = pack2(sm[2*wc+2][rn], sm[2*wc+3][rn]);
    o.z = pack2(sm[2*wc+4][rn], sm[2*wc+5][rn]);
    o.w = pack2(sm[2*wc+6][rn], sm[2*wc+7][rn]);
    *reinterpret_cast<uint4*>(Wp + (size_t)(n0 + rn) * (K >> 1) + (k0 >> 1) + wc) = o;
}

// ------------------- V pack: half [NTOK][E] -> token-pair words [NTOK/2][E] ----
__global__ __launch_bounds__(256) void vpack_kernel(
    const uint32_t* __restrict__ Vh, uint32_t* __restrict__ Vp)
{
    int gid = blockIdx.x * 256 + threadIdx.x;
    int pg = gid >> 8;
    int n = (gid & 255) * 4;
    uint2 a = *reinterpret_cast<const uint2*>(Vh + (size_t)(2 * pg) * 512 + (n >> 1));
    uint2 b = *reinterpret_cast<const uint2*>(Vh + (size_t)(2 * pg + 1) * 512 + (n >> 1));
    uint4 o;
    o.x = (a.x & 0xFFFFu) | (b.x << 16);
    o.y = (a.x >> 16)     | (b.x & 0xFFFF0000u);
    o.z = (a.y & 0xFFFFu) | (b.y << 16);
    o.w = (a.y >> 16)     | (b.y & 0xFFFF0000u);
    *reinterpret_cast<uint4*>(Vp + (size_t)pg * 1024 + n) = o;
}

// ------------------- LayerNorm (half out; optional raw fp32 out2) -------------------
__global__ __launch_bounds__(256) void ln_kernel(
    const float* __restrict__ in, uint32_t* __restrict__ outh, float* __restrict__ out2,
    const float* __restrict__ gw, const float* __restrict__ gb)
{
    int row = blockIdx.x;
    int tid = threadIdx.x;
    const float4* inr = reinterpret_cast<const float4*>(in + (size_t)row * EDIM);
    float4 v = inr[tid];
    float s  = v.x + v.y + v.z + v.w;
    float sq = v.x*v.x + v.y*v.y + v.z*v.z + v.w*v.w;

    int lane = tid & 31, warp = tid >> 5;
    #pragma unroll
    for (int o = 16; o > 0; o >>= 1) {
        s  += __shfl_xor_sync(0xffffffffu, s, o);
        sq += __shfl_xor_sync(0xffffffffu, sq, o);
    }
    __shared__ float rs[8], rq[8];
    if (lane == 0) { rs[warp] = s; rq[warp] = sq; }
    __syncthreads();
    if (warp == 0) {
        float s2 = (lane < 8) ? rs[lane] : 0.0f;
        float q2 = (lane < 8) ? rq[lane] : 0.0f;
        #pragma unroll
        for (int o = 4; o > 0; o >>= 1) {
            s2 += __shfl_xor_sync(0xffffffffu, s2, o);
            q2 += __shfl_xor_sync(0xffffffffu, q2, o);
        }
        if (lane == 0) { rs[0] = s2; rq[0] = q2; }
    }
    __syncthreads();
    float mean = rs[0] * (1.0f / EDIM);
    float var  = rq[0] * (1.0f / EDIM) - mean * mean;
    float rstd = rsqrtf(var + 1e-5f);

    float4 gg = reinterpret_cast<const float4*>(gw)[tid];
    float4 bb = reinterpret_cast<const float4*>(gb)[tid];
    float4 o4;
    o4.x = (v.x - mean) * rstd * gg.x + bb.x;
    o4.y = (v.y - mean) * rstd * gg.y + bb.y;
    o4.z = (v.z - mean) * rstd * gg.z + bb.z;
    o4.w = (v.w - mean) * rstd * gg.w + bb.w;
    if (out2) reinterpret_cast<float4*>(out2 + (size_t)row * EDIM)[tid] = o4;
    uint2 w2;
    w2.x = pack2(o4.x, o4.y);
    w2.y = pack2(o4.z, o4.w);
    reinterpret_cast<uint2*>(outh + (size_t)row * 512)[tid] = w2;
}

// ------------------- flash attention fp16 + ldmatrix Q/K ---------------------
// grid (16,16,4), 256 thr, 2 CTAs/SM. Warp tile 16 q-rows x 64 kv.
// smem words: Qs [0,4608) 128x36; Ks [4608,9216) 2 x 64x36; Vs [9216,13824) 2 x 32x72.
#define FLASH_SMEM_WORDS 13824

__global__ __launch_bounds__(256, 2) void flash_kernel(
    const __half* __restrict__ Qg, const __half* __restrict__ Kg,
    const uint32_t* __restrict__ Vp, const float* __restrict__ maskf,
    uint32_t* __restrict__ Og)
{
    extern __shared__ uint32_t smu[];
    uint32_t* Qs = smu;
    uint32_t* Ks = smu + 4608;
    uint32_t* Vs = smu + 9216;
    uint32_t smbase = (uint32_t)__cvta_generic_to_shared(smu);

    int qt = blockIdx.x, h = blockIdx.y, b = blockIdx.z;
    int tokbase = b * SEQ + qt * 128;
    const uint32_t* Qw  = (const uint32_t*)Qg + (size_t)tokbase * 512 + h * 32;
    const __half*   Kb0 = Kg + (size_t)b * SEQ * EDIM + h * HDIM;
    const uint32_t* Vp0 = Vp + (size_t)(b * SEQ / 2) * EDIM + h * HDIM;
    const float*    mfb = maskf + (size_t)b * SEQ;

    int tid = threadIdx.x, w = tid >> 5, lane = tid & 31;
    int g = lane >> 2, t4 = lane & 3;
    int r0 = w * 16 + g;

    // ldmatrix per-lane offsets (words)
    uint32_t ml = lane >> 3, rl = lane & 7;
    uint32_t qoff = (w * 16 + (ml & 1) * 8 + rl) * 36 + (ml >> 1) * 4;
    uint32_t koff = ((ml >> 1) * 8 + rl) * 36 + (ml & 1) * 4;

    // stage Q (scale by 0.125, exact in half)
    __half2 sc = __float2half2_rn(0.125f);
    #pragma unroll
    for (int it = 0; it < 8; it++) {
        int idx = tid + it * 256;
        int r = idx >> 4, c = (idx & 15) * 2;
        uint2 v = *reinterpret_cast<const uint2*>(Qw + (size_t)r * 512 + c);
        __half2 h0 = __hmul2(*reinterpret_cast<__half2*>(&v.x), sc);
        __half2 h1 = __hmul2(*reinterpret_cast<__half2*>(&v.y), sc);
        uint2 o;
        o.x = *reinterpret_cast<uint32_t*>(&h0);
        o.y = *reinterpret_cast<uint32_t*>(&h1);
        *reinterpret_cast<uint2*>(&Qs[r * 36 + c]) = o;
    }

    auto issue_kv = [&](int j, int buf) {
        const __half* Kc = Kb0 + (size_t)j * 64 * EDIM;
        const uint32_t* Vc = Vp0 + (size_t)(j * 32) * EDIM;
        uint32_t* Kd = Ks + buf * 2304;
        uint32_t* Vd = Vs + buf * 2304;
        #pragma unroll
        for (int it = 0; it < 2; it++) {
            int idx = tid + it * 256;
            int r = idx >> 3, c = idx & 7;
            CP16(&Kd[r * 36 + c * 4], Kc + (size_t)r * EDIM + c * 8);
        }
        #pragma unroll
        for (int it = 0; it < 2; it++) {
            int idx = tid + it * 256;
            int p = idx >> 4, c = idx & 15;
            CP16(&Vd[p * 72 + c * 4], Vc + (size_t)p * EDIM + c * 4);
        }
    };

    issue_kv(0, 0);
    CP_COMMIT();

    float m0 = -1e30f, m1 = -1e30f, l0 = 0.0f, l1 = 0.0f;
    float oacc[8][4];
    #pragma unroll
    for (int nf = 0; nf < 8; nf++)
        #pragma unroll
        for (int i = 0; i < 4; i++) oacc[nf][i] = 0.0f;

    const int NCH = SEQ / 64;
    for (int j = 0; j < NCH; j++) {
        int buf = j & 1;
        if (j + 1 < NCH) { issue_kv(j + 1, buf ^ 1); CP_COMMIT(); CP_WAIT1(); }
        else             { CP_WAIT0(); }
        __syncthreads();

        const uint32_t* Vb = Vs + buf * 2304;
        uint32_t Qb = smbase + qoff * 4;
        uint32_t Kb = smbase + (4608 + buf * 2304 + koff) * 4;

        // ---- S = (Q*0.125) @ K^T ----
        float sacc[8][4];
        #pragma unroll
        for (int nf = 0; nf < 8; nf++)
            #pragma unroll
            for (int i = 0; i < 4; i++) sacc[nf][i] = 0.0f;

        #pragma unroll
        for (int s = 0; s < 4; s++) {
            uint32_t afr[4];
            LDSM4(afr[0], afr[1], afr[2], afr[3], Qb + 8 * s * 4);
            uint32_t bfr[8][2];
            #pragma unroll
            for (int nf2 = 0; nf2 < 4; nf2++) {
                LDSM4(bfr[2*nf2][0], bfr[2*nf2][1], bfr[2*nf2+1][0], bfr[2*nf2+1][1],
                      Kb + (nf2 * 576 + 8 * s) * 4);
            }
            #pragma unroll
            for (int nf = 0; nf < 8; nf++)
                mma16(sacc[nf], afr, bfr[nf]);
        }

        // ---- mask + register softmax ----
        const float2* mf2 = (const float2*)(mfb + j * 64);
        float mx0 = -1e30f, mx1 = -1e30f;
        #pragma unroll
        for (int nf = 0; nf < 8; nf++) {
            float2 md = mf2[nf * 4 + t4];
            sacc[nf][0] += md.x; sacc[nf][1] += md.y;
            sacc[nf][2] += md.x; sacc[nf][3] += md.y;
            mx0 = fmaxf(mx0, fmaxf(sacc[nf][0], sacc[nf][1]));
            mx1 = fmaxf(mx1, fmaxf(sacc[nf][2], sacc[nf][3]));
        }
        mx0 = fmaxf(mx0, __shfl_xor_sync(0xffffffffu, mx0, 1));
        mx0 = fmaxf(mx0, __shfl_xor_sync(0xffffffffu, mx0, 2));
        mx1 = fmaxf(mx1, __shfl_xor_sync(0xffffffffu, mx1, 1));
        mx1 = fmaxf(mx1, __shfl_xor_sync(0xffffffffu, mx1, 2));
        float mn0 = fmaxf(m0, mx0), mn1 = fmaxf(m1, mx1);
        float c0 = __expf(m0 - mn0), c1 = __expf(m1 - mn1);
        float s0 = 0.0f, s1 = 0.0f;
        uint32_t ppk0[8], ppk1[8];
        #pragma unroll
        for (int nf = 0; nf < 8; nf++) {
            float p00 = __expf(sacc[nf][0] - mn0);
            float p01 = __expf(sacc[nf][1] - mn0);
            float p10 = __expf(sacc[nf][2] - mn1);
            float p11 = __expf(sacc[nf][3] - mn1);
            s0 += p00 + p01; s1 += p10 + p11;
            ppk0[nf] = pack2(p00, p01);
            ppk1[nf] = pack2(p10, p11);
        }
        s0 += __shfl_xor_sync(0xffffffffu, s0, 1);
        s0 += __shfl_xor_sync(0xffffffffu, s0, 2);
        s1 += __shfl_xor_sync(0xffffffffu, s1, 1);
        s1 += __shfl_xor_sync(0xffffffffu, s1, 2);
        l0 = l0 * c0 + s0; l1 = l1 * c1 + s1;
        m0 = mn0; m1 = mn1;

        // ---- rescale O, accumulate P @ V ----
        #pragma unroll
        for (int nf = 0; nf < 8; nf++) {
            oacc[nf][0] *= c0; oacc[nf][1] *= c0;
            oacc[nf][2] *= c1; oacc[nf][3] *= c1;
        }
        #pragma unroll
        for (int s = 0; s < 4; s++) {
            uint32_t afr[4];
            afr[0] = ppk0[2 * s];
            afr[1] = ppk1[2 * s];
            afr[2] = ppk0[2 * s + 1];
            afr[3] = ppk1[2 * s + 1];
            uint32_t bfr[8][2];
            #pragma unroll
            for (int nf = 0; nf < 8; nf++) {
                int n = nf * 8 + g;
                bfr[nf][0] = Vb[(8 * s + t4) * 72 + n];
                bfr[nf][1] = Vb[(8 * s + 4 + t4) * 72 + n];
            }
            #pragma unroll
            for (int nf = 0; nf < 8; nf++)
                mma16(oacc[nf], afr, bfr[nf]);
        }
        __syncthreads();
    }

    float inv0 = 1.0f / l0, inv1 = 1.0f / l1;
    uint32_t* Ob = Og + (size_t)tokbase * 512 + h * 32;
    #pragma unroll
    for (int nf = 0; nf < 8; nf++) {
        int cw = nf * 4 + t4;
        Ob[(size_t)r0 * 512 + cw]       = pack2(oacc[nf][0] * inv0, oacc[nf][1] * inv0);
        Ob[(size_t)(r0 + 8) * 512 + cw] = pack2(oacc[nf][2] * inv1, oacc[nf][3] * inv1);
    }
}

// ---- fp16 NN GEMM, ldmatrix both operands: CTA 128x128, warp 64x32, BK=64 ----
// A: half [M][K]; Bp: packed transposed [N][K/2] words.
// smem: As 3 x 128x36, Bs 3 x 128x36 (n-major).
#define GEMM_SMEM_WORDS (6*4608)

template<int EPI, int OUTH>
__global__ __launch_bounds__(256, 2) void gemm_h(
    const __half* __restrict__ A, const uint32_t* __restrict__ Bp, void* __restrict__ Cv,
    int K, int N, const float* __restrict__ bias, const float* __restrict__ res)
{
    extern __shared__ uint32_t smu[];
    uint32_t* As = smu;              // 3 x 128 x 36
    uint32_t* Bs = smu + 3 * 4608;   // 3 x 128 x 36 (rows = n)
    uint32_t smbase = (uint32_t)__cvta_generic_to_shared(smu);

    int m0 = blockIdx.y * 128, n0 = blockIdx.x * 128;
    int tid = threadIdx.x, warp = tid >> 5, lane = tid & 31;
    int wm = (warp >> 2) * 64, wn = (warp & 3) * 32;
    int g = lane >> 2, t4 = lane & 3;

    // ldmatrix per-lane offsets (words within stage)
    uint32_t ml = lane >> 3, rl = lane & 7;
    uint32_t aoff = (wm + (ml & 1) * 8 + rl) * 36 + (ml >> 1) * 4;
    uint32_t boff = (wn + (ml >> 1) * 8 + rl) * 36 + (ml & 1) * 4;

    const int T = K >> 6;
    const int Kw = K >> 1;

    auto issue = [&](int t) {
        int s = t % 3;
        int k0 = t << 6, p0 = t << 5;
        uint32_t* Ad = As + s * 4608;
        uint32_t* Bd = Bs + s * 4608;
        #pragma unroll
        for (int it = 0; it < 4; it++) {
            int idx = tid + it * 256;
            int r = idx >> 3, c = idx & 7;
            CP16(&Ad[r * 36 + c * 4], A + (size_t)(m0 + r) * K + k0 + c * 8);
        }
        #pragma unroll
        for (int it = 0; it < 4; it++) {
            int idx = tid + it * 256;
            int r = idx >> 3, c = idx & 7;
            CP16(&Bd[r * 36 + c * 4], Bp + (size_t)(n0 + r) * Kw + p0 + c * 4);
        }
    };

    float acc[4][4][4];
    #pragma unroll
    for (int a = 0; a < 4; a++)
        #pragma unroll
        for (int c = 0; c < 4; c++)
            #pragma unroll
            for (int i = 0; i < 4; i++) acc[a][c][i] = 0.0f;

    issue(0);
    CP_COMMIT();

    for (int t = 0; t < T; t++) {
        if (t + 1 < T) { issue(t + 1); CP_COMMIT(); CP_WAIT1(); }
        else           { CP_WAIT0(); }
        __syncthreads();

        uint32_t Ab = smbase + ((t % 3) * 4608 + aoff) * 4;
        uint32_t Bb = smbase + ((3 + (t % 3)) * 4608 + boff) * 4;
        #pragma unroll
        for (int s = 0; s < 4; s++) {     // 4 k16 steps per k64 tile
            uint32_t afr[4][4], bfr[4][2];
            #pragma unroll
            for (int mf = 0; mf < 4; mf++)
                LDSM4(afr[mf][0], afr[mf][1], afr[mf][2], afr[mf][3],
                      Ab + (mf * 576 + 8 * s) * 4);
            LDSM4(bfr[0][0], bfr[0][1], bfr[1][0], bfr[1][1], Bb + 8 * s * 4);
            LDSM4(bfr[2][0], bfr[2][1], bfr[3][0], bfr[3][1], Bb + (16 * 36 + 8 * s) * 4);
            #pragma unroll
            for (int mf = 0; mf < 4; mf++)
                #pragma unroll
                for (int nf = 0; nf < 4; nf++)
                    mma16(acc[mf][nf], afr[mf], bfr[nf]);
        }
    }

    #pragma unroll
    for (int mf = 0; mf < 4; mf++) {
        #pragma unroll
        for (int nf = 0; nf < 4; nf++) {
            int m = m0 + wm + mf * 16 + g;
            int n = n0 + wn + nf * 8 + 2 * t4;
            float2 v0 = make_float2(acc[mf][nf][0], acc[mf][nf][1]);
            float2 v1 = make_float2(acc[mf][nf][2], acc[mf][nf][3]);
            if (EPI >= 1) {
                float2 bz = *reinterpret_cast<const float2*>(bias + n);
                v0.x += bz.x; v0.y += bz.y;
                v1.x += bz.x; v1.y += bz.y;
            }
            if (EPI == 2) {
                float2 r0 = *reinterpret_cast<const float2*>(res + (size_t)m * N + n);
                float2 r1 = *reinterpret_cast<const float2*>(res + (size_t)(m + 8) * N + n);
                v0.x += r0.x; v0.y += r0.y;
                v1.x += r1.x; v1.y += r1.y;
            }
            if (EPI == 3) {
                v0.x = gelu_exact(v0.x); v0.y = gelu_exact(v0.y);
                v1.x = gelu_exact(v1.x); v1.y = gelu_exact(v1.y);
            }
            if (OUTH) {
                uint32_t* Ch = (uint32_t*)Cv;
                Ch[((size_t)m * N + n) >> 1]       = pack2(v0.x, v0.y);
                Ch[((size_t)(m + 8) * N + n) >> 1] = pack2(v1.x, v1.y);
            } else {
                float* Cf = (float*)Cv;
                *reinterpret_cast<float2*>(Cf + (size_t)m * N + n)       = v0;
                *reinterpret_cast<float2*>(Cf + (size_t)(m + 8) * N + n) = v1;
            }
        }
    }
}

// ------------------- host launch -------------------
static void* sym_addr(const void* symbol) {
    void* p = nullptr;
    cudaGetSymbolAddress(&p, symbol);
    return p;
}

extern "C" void kernel_launch(void* const* d_in, const int* in_sizes, int n_in,
                              void* d_out, int out_size) {
    (void)in_sizes; (void)n_in; (void)out_size;
    const float* value = (const float*)d_in[0];
    const float* key   = (const float*)d_in[1];
    const float* query = (const float*)d_in[2];
    const int*   mask  = (const int*)  d_in[3];
    const float* Wv    = (const float*)d_in[4];
    const float* Wk    = (const float*)d_in[5];
    const float* Wq    = (const float*)d_in[6];
    const float* Wo    = (const float*)d_in[7];
    const float* bo    = (const float*)d_in[8];
    const float* ln1_g = (const float*)d_in[9];
    const float* ln1_b = (const float*)d_in[10];
    const float* ln2_g = (const float*)d_in[11];
    const float* ln2_b = (const float*)d_in[12];
    const float* lnf_g = (const float*)d_in[13];
    const float* lnf_b = (const float*)d_in[14];
    const float* W1    = (const float*)d_in[15];
    const float* b1    = (const float*)d_in[16];
    const float* W2    = (const float*)d_in[17];
    const float* b2    = (const float*)d_in[18];
    float* out = (float*)d_out;

    __half*   p_qln_h = (__half*)sym_addr(g_qln_h);
    float*    p_qln   = (float*)sym_addr(g_qln);
    __half*   p_vln_h = (__half*)sym_addr(g_vln_h);
    __half*   p_kln_h = (__half*)sym_addr(g_kln_h);
    __half*   p_Q     = (__half*)sym_addr(g_Q);
    __half*   p_K     = (__half*)sym_addr(g_K);
    __half*   p_V     = (__half*)sym_addr(g_V);
    uint32_t* p_Vp    = (uint32_t*)sym_addr(g_Vp);
    __half*   p_att   = (__half*)sym_addr(g_att);
    float*    p_x     = (float*)sym_addr(g_x);
    __half*   p_hh    = (__half*)sym_addr(g_hh);
    __half*   p_ff    = (__half*)sym_addr(g_ff);
    float*    p_mf    = (float*)sym_addr(g_maskf);
    uint32_t* p_Wq    = (uint32_t*)sym_addr(g_Wq);
    uint32_t* p_Wk    = (uint32_t*)sym_addr(g_Wk);
    uint32_t* p_Wv    = (uint32_t*)sym_addr(g_Wv);
    uint32_t* p_Wo    = (uint32_t*)sym_addr(g_Wo);
    uint32_t* p_W1    = (uint32_t*)sym_addr(g_W1);
    uint32_t* p_W2    = (uint32_t*)sym_addr(g_W2);

    const int GSM = GEMM_SMEM_WORDS * 4;     // 110592
    const int FSM = FLASH_SMEM_WORDS * 4;    // 55296
    cudaFuncSetAttribute(gemm_h<0,1>, cudaFuncAttributeMaxDynamicSharedMemorySize, GSM);
    cudaFuncSetAttribute(gemm_h<2,0>, cudaFuncAttributeMaxDynamicSharedMemorySize, GSM);
    cudaFuncSetAttribute(gemm_h<3,1>, cudaFuncAttributeMaxDynamicSharedMemorySize, GSM);
    cudaFuncSetAttribute(flash_kernel, cudaFuncAttributeMaxDynamicSharedMemorySize, FSM);

    // 0) mask addends + transposed weight packing
    maskf_kernel<<<NTOK / 256, 256>>>(mask, p_mf);
    wpackT_kernel<<<dim3(EDIM/32, EDIM/64), 256>>>(Wq, p_Wq, EDIM, EDIM);
    wpackT_kernel<<<dim3(EDIM/32, EDIM/64), 256>>>(Wk, p_Wk, EDIM, EDIM);
    wpackT_kernel<<<dim3(EDIM/32, EDIM/64), 256>>>(Wv, p_Wv, EDIM, EDIM);
    wpackT_kernel<<<dim3(EDIM/32, EDIM/64), 256>>>(Wo, p_Wo, EDIM, EDIM);
    wpackT_kernel<<<dim3(FFDIM/32, EDIM/64), 256>>>(W1, p_W1, EDIM, FFDIM);
    wpackT_kernel<<<dim3(EDIM/32, FFDIM/64), 256>>>(W2, p_W2, FFDIM, EDIM);

    // 1) pre-norms (half outputs; raw fp32 LN1(q) for residual)
    ln_kernel<<<NTOK, 256>>>(query, (uint32_t*)p_qln_h, p_qln, ln1_g, ln1_b);
    ln_kernel<<<NTOK, 256>>>(value, (uint32_t*)p_vln_h, nullptr, ln2_g, ln2_b);
    ln_kernel<<<NTOK, 256>>>(key,   (uint32_t*)p_kln_h, nullptr, ln2_g, ln2_b);

    // 2) QKV projections (half out)
    dim3 gProj(EDIM / 128, NTOK / 128, 1);
    gemm_h<0,1><<<gProj, 256, GSM>>>(p_qln_h, p_Wq, p_Q, EDIM, EDIM, nullptr, nullptr);
    gemm_h<0,1><<<gProj, 256, GSM>>>(p_kln_h, p_Wk, p_K, EDIM, EDIM, nullptr, nullptr);
    gemm_h<0,1><<<gProj, 256, GSM>>>(p_vln_h, p_Wv, p_V, EDIM, EDIM, nullptr, nullptr);

    // 2b) pack V into token pairs for PV mma B-operand
    vpack_kernel<<<NTOK/2*EDIM/4/256, 256>>>((uint32_t*)p_V, p_Vp);

    // 3) fused attention (half out)
    dim3 gF(SEQ / 128, NHEAD, BATCH);
    flash_kernel<<<gF, 256, FSM>>>(p_Q, p_K, p_Vp, p_mf, (uint32_t*)p_att);

    // 4) x = att @ Wo + bo + LN1(q)_raw  (fp32 out)
    gemm_h<2,0><<<gProj, 256, GSM>>>(p_att, p_Wo, p_x, EDIM, EDIM, bo, p_qln);

    // 5) h = LN_f(x) (half out)
    ln_kernel<<<NTOK, 256>>>(p_x, (uint32_t*)p_hh, nullptr, lnf_g, lnf_b);

    // 6) ff = gelu(h @ W1 + b1) (half out)
    dim3 gF1(FFDIM / 128, NTOK / 128, 1);
    gemm_h<3,1><<<gF1, 256, GSM>>>(p_hh, p_W1, p_ff, EDIM, FFDIM, b1, nullptr);

    // 7) out = ff @ W2 + b2 + x (fp32 out)
    dim3 gF2(EDIM / 128, NTOK / 128, 1);
    gemm_h<2,0><<<gF2, 256, GSM>>>(p_ff, p_W2, out, FFDIM, EDIM, b2, p_x);
}

// round 12
// speedup vs baseline: 2.9301x; 1.0050x over previous
#include <cuda_runtime.h>
#include <cuda_fp16.h>
#include <cstdint>
#include <cstddef>

#define EDIM 1024
#define NHEAD 16
#define HDIM 64
#define FFDIM 4096
#define BATCH 4
#define SEQ 2048
#define NTOK (BATCH*SEQ)   // 8192

// ------------------- scratch (device globals; no allocations) -------------------
__device__ __half   g_qln_h[(size_t)NTOK*EDIM];
__device__ float    g_qln  [(size_t)NTOK*EDIM];   // raw fp32 residual
__device__ __half   g_vln_h[(size_t)NTOK*EDIM];
__device__ __half   g_kln_h[(size_t)NTOK*EDIM];
__device__ __half   g_Q [(size_t)NTOK*EDIM];
__device__ __half   g_K [(size_t)NTOK*EDIM];
__device__ __half   g_V [(size_t)NTOK*EDIM];
__device__ uint32_t g_Vp[(size_t)NTOK/2*EDIM];    // token-pair packed V
__device__ __half   g_att[(size_t)NTOK*EDIM];
__device__ float    g_x [(size_t)NTOK*EDIM];
__device__ __half   g_hh[(size_t)NTOK*EDIM];
__device__ __half   g_ff[(size_t)NTOK*FFDIM];
__device__ float    g_maskf[(size_t)BATCH*SEQ];
// weights packed TRANSPOSED: [N][K/2] half2-k-pair words
__device__ uint32_t g_Wq[(size_t)EDIM*EDIM/2];
__device__ uint32_t g_Wk[(size_t)EDIM*EDIM/2];
__device__ uint32_t g_Wv[(size_t)EDIM*EDIM/2];
__device__ uint32_t g_Wo[(size_t)EDIM*EDIM/2];
__device__ uint32_t g_W1[(size_t)FFDIM*EDIM/2];   // [4096][512]
__device__ uint32_t g_W2[(size_t)EDIM*FFDIM/2];   // [1024][2048]

// ------------------- helpers -------------------
__device__ __forceinline__ uint32_t pack2(float lo, float hi) {
    __half2 h = __floats2half2_rn(lo, hi);
    return *reinterpret_cast<uint32_t*>(&h);
}

__device__ __forceinline__ void mma16(float* c, const uint32_t* a, const uint32_t* b) {
    asm volatile(
        "mma.sync.aligned.m16n8k16.row.col.f32.f16.f16.f32 "
        "{%0,%1,%2,%3},{%4,%5,%6,%7},{%8,%9},{%0,%1,%2,%3};\n"
        : "+f"(c[0]), "+f"(c[1]), "+f"(c[2]), "+f"(c[3])
        : "r"(a[0]), "r"(a[1]), "r"(a[2]), "r"(a[3]), "r"(b[0]), "r"(b[1]));
}

#define LDSM4(R0,R1,R2,R3,ADDR) \
    asm volatile("ldmatrix.sync.aligned.m8n8.x4.shared.b16 {%0,%1,%2,%3}, [%4];\n" \
        : "=r"(R0), "=r"(R1), "=r"(R2), "=r"(R3) : "r"(ADDR))

__device__ __forceinline__ float gelu_exact(float v) {
    return 0.5f * v * (1.0f + erff(v * 0.70710678118654752f));
}

#define CP16(dst_sm, src_g) \
    asm volatile("cp.async.cg.shared.global [%0], [%1], 16;\n" :: \
        "r"((uint32_t)__cvta_generic_to_shared(dst_sm)), "l"(src_g))
#define CP_COMMIT() asm volatile("cp.async.commit_group;\n")
#define CP_WAIT1()  asm volatile("cp.async.wait_group 1;\n")
#define CP_WAIT0()  asm volatile("cp.async.wait_group 0;\n")

// ------------------- mask -> float addend -------------------
__global__ __launch_bounds__(256) void maskf_kernel(
    const int* __restrict__ mask, float* __restrict__ mf)
{
    int i = blockIdx.x * 256 + threadIdx.x;
    mf[i] = (mask[i] == 0) ? -1e20f : 0.0f;
}

// ---- weight pack+transpose: fp32 [K][N] -> words [N][K/2] (k-pair minor) ----
// 32n x 256k tiles: 8 float4 load-iters (deep MLP), coalesced 128B store groups.
__global__ __launch_bounds__(256) void wpackT_kernel(
    const float* __restrict__ W, uint32_t* __restrict__ Wp, int K, int N)
{
    __shared__ float sm[256][33];
    int n0 = blockIdx.x * 32, k0 = blockIdx.y * 256;
    int tid = threadIdx.x;
    #pragma unroll
    for (int i = 0; i < 8; i++) {
        int idx = tid + i * 256;
        int r = idx >> 3, c4 = (idx & 7) * 4;
        float4 v = *reinterpret_cast<const float4*>(W + (size_t)(k0 + r) * N + n0 + c4);
        sm[r][c4] = v.x; sm[r][c4+1] = v.y; sm[r][c4+2] = v.z; sm[r][c4+3] = v.w;
    }
    __syncthreads();
    int Kw = K >> 1;
    #pragma unroll
    for (int i = 0; i < 4; i++) {
        int idx = tid + i * 256;
        int wc = (idx & 7) * 4;          // word-in-group 0..28
        int n  = (idx >> 3) & 31;        // n-row
        int kb = idx >> 8;               // k-block 0..3 (64 k's each)
        int w  = kb * 32 + wc;           // word offset within 128-word tile
        uint4 o;
        o.x = pack2(sm[2*w  ][n], sm[2*w+1][n]);
        o.y = pack2(sm[2*w+2][n], sm[2*w+3][n]);
        o.z = pack2(sm[2*w+4][n], sm[2*w+5][n]);
        o.w = pack2(sm[2*w+6][n], sm[2*w+7][n]);
        *reinterpret_cast<uint4*>(Wp + (size_t)(n0 + n) * Kw + (k0 >> 1) + w) = o;
    }
}

// ------------------- V pack: half [NTOK][E] -> token-pair words [NTOK/2][E] ----
__global__ __launch_bounds__(256) void vpack_kernel(
    const uint32_t* __restrict__ Vh, uint32_t* __restrict__ Vp)
{
    int gid = blockIdx.x * 256 + threadIdx.x;
    int pg = gid >> 8;
    int n = (gid & 255) * 4;
    uint2 a = *reinterpret_cast<const uint2*>(Vh + (size_t)(2 * pg) * 512 + (n >> 1));
    uint2 b = *reinterpret_cast<const uint2*>(Vh + (size_t)(2 * pg + 1) * 512 + (n >> 1));
    uint4 o;
    o.x = (a.x & 0xFFFFu) | (b.x << 16);
    o.y = (a.x >> 16)     | (b.x & 0xFFFF0000u);
    o.z = (a.y & 0xFFFFu) | (b.y << 16);
    o.w = (a.y >> 16)     | (b.y & 0xFFFF0000u);
    *reinterpret_cast<uint4*>(Vp + (size_t)pg * 1024 + n) = o;
}

// ------------------- LayerNorm: warp-per-row, shuffle-only reduction ---------
// grid = NTOK/8, 256 threads (8 warps = 8 rows). half out; optional fp32 out2.
__global__ __launch_bounds__(256) void ln_kernel(
    const float* __restrict__ in, uint32_t* __restrict__ outh, float* __restrict__ out2,
    const float* __restrict__ gw, const float* __restrict__ gb)
{
    int warp = threadIdx.x >> 5, lane = threadIdx.x & 31;
    int row = blockIdx.x * 8 + warp;
    const float4* inr = reinterpret_cast<const float4*>(in + (size_t)row * EDIM);

    float4 v[8];
    float s = 0.0f, sq = 0.0f;
    #pragma unroll
    for (int i = 0; i < 8; i++) {
        v[i] = inr[lane + 32 * i];
        s  += v[i].x + v[i].y + v[i].z + v[i].w;
        sq += v[i].x*v[i].x + v[i].y*v[i].y + v[i].z*v[i].z + v[i].w*v[i].w;
    }
    #pragma unroll
    for (int o = 16; o > 0; o >>= 1) {
        s  += __shfl_xor_sync(0xffffffffu, s, o);
        sq += __shfl_xor_sync(0xffffffffu, sq, o);
    }
    float mean = s * (1.0f / EDIM);
    float var  = sq * (1.0f / EDIM) - mean * mean;
    float rstd = rsqrtf(var + 1e-5f);

    const float4* gw4 = reinterpret_cast<const float4*>(gw);
    const float4* gb4 = reinterpret_cast<const float4*>(gb);
    #pragma unroll
    for (int i = 0; i < 8; i++) {
        float4 gg = gw4[lane + 32 * i];
        float4 bb = gb4[lane + 32 * i];
        float4 o4;
        o4.x = (v[i].x - mean) * rstd * gg.x + bb.x;
        o4.y = (v[i].y - mean) * rstd * gg.y + bb.y;
        o4.z = (v[i].z - mean) * rstd * gg.z + bb.z;
        o4.w = (v[i].w - mean) * rstd * gg.w + bb.w;
        if (out2)
            reinterpret_cast<float4*>(out2 + (size_t)row * EDIM)[lane + 32 * i] = o4;
        uint2 w2;
        w2.x = pack2(o4.x, o4.y);
        w2.y = pack2(o4.z, o4.w);
        reinterpret_cast<uint2*>(outh + (size_t)row * 512)[lane + 32 * i] = w2;
    }
}

// ------------------- flash attention fp16 + ldmatrix Q/K ---------------------
// grid (16,16,4), 256 thr, 2 CTAs/SM. Warp tile 16 q-rows x 64 kv.
// smem words: Qs [0,4608) 128x36; Ks [4608,9216) 2 x 64x36; Vs [9216,13824) 2 x 32x72.
#define FLASH_SMEM_WORDS 13824

__global__ __launch_bounds__(256, 2) void flash_kernel(
    const __half* __restrict__ Qg, const __half* __restrict__ Kg,
    const uint32_t* __restrict__ Vp, const float* __restrict__ maskf,
    uint32_t* __restrict__ Og)
{
    extern __shared__ uint32_t smu[];
    uint32_t* Qs = smu;
    uint32_t* Ks = smu + 4608;
    uint32_t* Vs = smu + 9216;
    uint32_t smbase = (uint32_t)__cvta_generic_to_shared(smu);

    int qt = blockIdx.x, h = blockIdx.y, b = blockIdx.z;
    int tokbase = b * SEQ + qt * 128;
    const uint32_t* Qw  = (const uint32_t*)Qg + (size_t)tokbase * 512 + h * 32;
    const __half*   Kb0 = Kg + (size_t)b * SEQ * EDIM + h * HDIM;
    const uint32_t* Vp0 = Vp + (size_t)(b * SEQ / 2) * EDIM + h * HDIM;
    const float*    mfb = maskf + (size_t)b * SEQ;

    int tid = threadIdx.x, w = tid >> 5, lane = tid & 31;
    int g = lane >> 2, t4 = lane & 3;
    int r0 = w * 16 + g;

    // ldmatrix per-lane offsets (words)
    uint32_t ml = lane >> 3, rl = lane & 7;
    uint32_t qoff = (w * 16 + (ml & 1) * 8 + rl) * 36 + (ml >> 1) * 4;
    uint32_t koff = ((ml >> 1) * 8 + rl) * 36 + (ml & 1) * 4;

    // stage Q (scale by 0.125, exact in half)
    __half2 sc = __float2half2_rn(0.125f);
    #pragma unroll
    for (int it = 0; it < 8; it++) {
        int idx = tid + it * 256;
        int r = idx >> 4, c = (idx & 15) * 2;
        uint2 v = *reinterpret_cast<const uint2*>(Qw + (size_t)r * 512 + c);
        __half2 h0 = __hmul2(*reinterpret_cast<__half2*>(&v.x), sc);
        __half2 h1 = __hmul2(*reinterpret_cast<__half2*>(&v.y), sc);
        uint2 o;
        o.x = *reinterpret_cast<uint32_t*>(&h0);
        o.y = *reinterpret_cast<uint32_t*>(&h1);
        *reinterpret_cast<uint2*>(&Qs[r * 36 + c]) = o;
    }

    auto issue_kv = [&](int j, int buf) {
        const __half* Kc = Kb0 + (size_t)j * 64 * EDIM;
        const uint32_t* Vc = Vp0 + (size_t)(j * 32) * EDIM;
        uint32_t* Kd = Ks + buf * 2304;
        uint32_t* Vd = Vs + buf * 2304;
        #pragma unroll
        for (int it = 0; it < 2; it++) {
            int idx = tid + it * 256;
            int r = idx >> 3, c = idx & 7;
            CP16(&Kd[r * 36 + c * 4], Kc + (size_t)r * EDIM + c * 8);
        }
        #pragma unroll
        for (int it = 0; it < 2; it++) {
            int idx = tid + it * 256;
            int p = idx >> 4, c = idx & 15;
            CP16(&Vd[p * 72 + c * 4], Vc + (size_t)p * EDIM + c * 4);
        }
    };

    issue_kv(0, 0);
    CP_COMMIT();

    float m0 = -1e30f, m1 = -1e30f, l0 = 0.0f, l1 = 0.0f;
    float oacc[8][4];
    #pragma unroll
    for (int nf = 0; nf < 8; nf++)
        #pragma unroll
        for (int i = 0; i < 4; i++) oacc[nf][i] = 0.0f;

    const int NCH = SEQ / 64;
    for (int j = 0; j < NCH; j++) {
        int buf = j & 1;
        if (j + 1 < NCH) { issue_kv(j + 1, buf ^ 1); CP_COMMIT(); CP_WAIT1(); }
        else             { CP_WAIT0(); }
        __syncthreads();

        const uint32_t* Vb = Vs + buf * 2304;
        uint32_t Qb = smbase + qoff * 4;
        uint32_t Kb = smbase + (4608 + buf * 2304 + koff) * 4;

        // ---- S = (Q*0.125) @ K^T ----
        float sacc[8][4];
        #pragma unroll
        for (int nf = 0; nf < 8; nf++)
            #pragma unroll
            for (int i = 0; i < 4; i++) sacc[nf][i] = 0.0f;

        #pragma unroll
        for (int s = 0; s < 4; s++) {
            uint32_t afr[4];
            LDSM4(afr[0], afr[1], afr[2], afr[3], Qb + 8 * s * 4);
            uint32_t bfr[8][2];
            #pragma unroll
            for (int nf2 = 0; nf2 < 4; nf2++) {
                LDSM4(bfr[2*nf2][0], bfr[2*nf2][1], bfr[2*nf2+1][0], bfr[2*nf2+1][1],
                      Kb + (nf2 * 576 + 8 * s) * 4);
            }
            #pragma unroll
            for (int nf = 0; nf < 8; nf++)
                mma16(sacc[nf], afr, bfr[nf]);
        }

        // ---- mask + register softmax ----
        const float2* mf2 = (const float2*)(mfb + j * 64);
        float mx0 = -1e30f, mx1 = -1e30f;
        #pragma unroll
        for (int nf = 0; nf < 8; nf++) {
            float2 md = mf2[nf * 4 + t4];
            sacc[nf][0] += md.x; sacc[nf][1] += md.y;
            sacc[nf][2] += md.x; sacc[nf][3] += md.y;
            mx0 = fmaxf(mx0, fmaxf(sacc[nf][0], sacc[nf][1]));
            mx1 = fmaxf(mx1, fmaxf(sacc[nf][2], sacc[nf][3]));
        }
        mx0 = fmaxf(mx0, __shfl_xor_sync(0xffffffffu, mx0, 1));
        mx0 = fmaxf(mx0, __shfl_xor_sync(0xffffffffu, mx0, 2));
        mx1 = fmaxf(mx1, __shfl_xor_sync(0xffffffffu, mx1, 1));
        mx1 = fmaxf(mx1, __shfl_xor_sync(0xffffffffu, mx1, 2));
        float mn0 = fmaxf(m0, mx0), mn1 = fmaxf(m1, mx1);
        float c0 = __expf(m0 - mn0), c1 = __expf(m1 - mn1);
        float s0 = 0.0f, s1 = 0.0f;
        uint32_t ppk0[8], ppk1[8];
        #pragma unroll
        for (int nf = 0; nf < 8; nf++) {
            float p00 = __expf(sacc[nf][0] - mn0);
            float p01 = __expf(sacc[nf][1] - mn0);
            float p10 = __expf(sacc[nf][2] - mn1);
            float p11 = __expf(sacc[nf][3] - mn1);
            s0 += p00 + p01; s1 += p10 + p11;
            ppk0[nf] = pack2(p00, p01);
            ppk1[nf] = pack2(p10, p11);
        }
        s0 += __shfl_xor_sync(0xffffffffu, s0, 1);
        s0 += __shfl_xor_sync(0xffffffffu, s0, 2);
        s1 += __shfl_xor_sync(0xffffffffu, s1, 1);
        s1 += __shfl_xor_sync(0xffffffffu, s1, 2);
        l0 = l0 * c0 + s0; l1 = l1 * c1 + s1;
        m0 = mn0; m1 = mn1;

        // ---- rescale O, accumulate P @ V ----
        #pragma unroll
        for (int nf = 0; nf < 8; nf++) {
            oacc[nf][0] *= c0; oacc[nf][1] *= c0;
            oacc[nf][2] *= c1; oacc[nf][3] *= c1;
        }
        #pragma unroll
        for (int s = 0; s < 4; s++) {
            uint32_t afr[4];
            afr[0] = ppk0[2 * s];
            afr[1] = ppk1[2 * s];
            afr[2] = ppk0[2 * s + 1];
            afr[3] = ppk1[2 * s + 1];
            uint32_t bfr[8][2];
            #pragma unroll
            for (int nf = 0; nf < 8; nf++) {
                int n = nf * 8 + g;
                bfr[nf][0] = Vb[(8 * s + t4) * 72 + n];
                bfr[nf][1] = Vb[(8 * s + 4 + t4) * 72 + n];
            }
            #pragma unroll
            for (int nf = 0; nf < 8; nf++)
                mma16(oacc[nf], afr, bfr[nf]);
        }
        __syncthreads();
    }

    float inv0 = 1.0f / l0, inv1 = 1.0f / l1;
    uint32_t* Ob = Og + (size_t)tokbase * 512 + h * 32;
    #pragma unroll
    for (int nf = 0; nf < 8; nf++) {
        int cw = nf * 4 + t4;
        Ob[(size_t)r0 * 512 + cw]       = pack2(oacc[nf][0] * inv0, oacc[nf][1] * inv0);
        Ob[(size_t)(r0 + 8) * 512 + cw] = pack2(oacc[nf][2] * inv1, oacc[nf][3] * inv1);
    }
}

// ---- fp16 NN GEMM, ldmatrix both operands: CTA 128x128, warp 64x32, BK=64 ----
// A: half [M][K]; Bp: packed transposed [N][K/2] words.
// smem: As 3 x 128x36, Bs 3 x 128x36 (n-major).
#define GEMM_SMEM_WORDS (6*4608)

template<int EPI, int OUTH>
__global__ __launch_bounds__(256, 2) void gemm_h(
    const __half* __restrict__ A, const uint32_t* __restrict__ Bp, void* __restrict__ Cv,
    int K, int N, const float* __restrict__ bias, const float* __restrict__ res)
{
    extern __shared__ uint32_t smu[];
    uint32_t* As = smu;              // 3 x 128 x 36
    uint32_t* Bs = smu + 3 * 4608;   // 3 x 128 x 36 (rows = n)
    uint32_t smbase = (uint32_t)__cvta_generic_to_shared(smu);

    int m0 = blockIdx.y * 128, n0 = blockIdx.x * 128;
    int tid = threadIdx.x, warp = tid >> 5, lane = tid & 31;
    int wm = (warp >> 2) * 64, wn = (warp & 3) * 32;
    int g = lane >> 2, t4 = lane & 3;

    // ldmatrix per-lane offsets (words within stage)
    uint32_t ml = lane >> 3, rl = lane & 7;
    uint32_t aoff = (wm + (ml & 1) * 8 + rl) * 36 + (ml >> 1) * 4;
    uint32_t boff = (wn + (ml >> 1) * 8 + rl) * 36 + (ml & 1) * 4;

    const int T = K >> 6;
    const int Kw = K >> 1;

    auto issue = [&](int t) {
        int s = t % 3;
        int k0 = t << 6, p0 = t << 5;
        uint32_t* Ad = As + s * 4608;
        uint32_t* Bd = Bs + s * 4608;
        #pragma unroll
        for (int it = 0; it < 4; it++) {
            int idx = tid + it * 256;
            int r = idx >> 3, c = idx & 7;
            CP16(&Ad[r * 36 + c * 4], A + (size_t)(m0 + r) * K + k0 + c * 8);
        }
        #pragma unroll
        for (int it = 0; it < 4; it++) {
            int idx = tid + it * 256;
            int r = idx >> 3, c = idx & 7;
            CP16(&Bd[r * 36 + c * 4], Bp + (size_t)(n0 + r) * Kw + p0 + c * 4);
        }
    };

    float acc[4][4][4];
    #pragma unroll
    for (int a = 0; a < 4; a++)
        #pragma unroll
        for (int c = 0; c < 4; c++)
            #pragma unroll
            for (int i = 0; i < 4; i++) acc[a][c][i] = 0.0f;

    issue(0);
    CP_COMMIT();

    for (int t = 0; t < T; t++) {
        if (t + 1 < T) { issue(t + 1); CP_COMMIT(); CP_WAIT1(); }
        else           { CP_WAIT0(); }
        __syncthreads();

        uint32_t Ab = smbase + ((t % 3) * 4608 + aoff) * 4;
        uint32_t Bb = smbase + ((3 + (t % 3)) * 4608 + boff) * 4;
        #pragma unroll
        for (int s = 0; s < 4; s++) {     // 4 k16 steps per k64 tile
            uint32_t afr[4][4], bfr[4][2];
            #pragma unroll
            for (int mf = 0; mf < 4; mf++)
                LDSM4(afr[mf][0], afr[mf][1], afr[mf][2], afr[mf][3],
                      Ab + (mf * 576 + 8 * s) * 4);
            LDSM4(bfr[0][0], bfr[0][1], bfr[1][0], bfr[1][1], Bb + 8 * s * 4);
            LDSM4(bfr[2][0], bfr[2][1], bfr[3][0], bfr[3][1], Bb + (16 * 36 + 8 * s) * 4);
            #pragma unroll
            for (int mf = 0; mf < 4; mf++)
                #pragma unroll
                for (int nf = 0; nf < 4; nf++)
                    mma16(acc[mf][nf], afr[mf], bfr[nf]);
        }
    }

    #pragma unroll
    for (int mf = 0; mf < 4; mf++) {
        #pragma unroll
        for (int nf = 0; nf < 4; nf++) {
            int m = m0 + wm + mf * 16 + g;
            int n = n0 + wn + nf * 8 + 2 * t4;
            float2 v0 = make_float2(acc[mf][nf][0], acc[mf][nf][1]);
            float2 v1 = make_float2(acc[mf][nf][2], acc[mf][nf][3]);
            if (EPI >= 1) {
                float2 bz = *reinterpret_cast<const float2*>(bias + n);
                v0.x += bz.x; v0.y += bz.y;
                v1.x += bz.x; v1.y += bz.y;
            }
            if (EPI == 2) {
                float2 r0 = *reinterpret_cast<const float2*>(res + (size_t)m * N + n);
                float2 r1 = *reinterpret_cast<const float2*>(res + (size_t)(m + 8) * N + n);
                v0.x += r0.x; v0.y += r0.y;
                v1.x += r1.x; v1.y += r1.y;
            }
            if (EPI == 3) {
                v0.x = gelu_exact(v0.x); v0.y = gelu_exact(v0.y);
                v1.x = gelu_exact(v1.x); v1.y = gelu_exact(v1.y);
            }
            if (OUTH) {
                uint32_t* Ch = (uint32_t*)Cv;
                Ch[((size_t)m * N + n) >> 1]       = pack2(v0.x, v0.y);
                Ch[((size_t)(m + 8) * N + n) >> 1] = pack2(v1.x, v1.y);
            } else {
                float* Cf = (float*)Cv;
                *reinterpret_cast<float2*>(Cf + (size_t)m * N + n)       = v0;
                *reinterpret_cast<float2*>(Cf + (size_t)(m + 8) * N + n) = v1;
            }
        }
    }
}

// ------------------- host launch -------------------
static void* sym_addr(const void* symbol) {
    void* p = nullptr;
    cudaGetSymbolAddress(&p, symbol);
    return p;
}

extern "C" void kernel_launch(void* const* d_in, const int* in_sizes, int n_in,
                              void* d_out, int out_size) {
    (void)in_sizes; (void)n_in; (void)out_size;
    const float* value = (const float*)d_in[0];
    const float* key   = (const float*)d_in[1];
    const float* query = (const float*)d_in[2];
    const int*   mask  = (const int*)  d_in[3];
    const float* Wv    = (const float*)d_in[4];
    const float* Wk    = (const float*)d_in[5];
    const float* Wq    = (const float*)d_in[6];
    const float* Wo    = (const float*)d_in[7];
    const float* bo    = (const float*)d_in[8];
    const float* ln1_g = (const float*)d_in[9];
    const float* ln1_b = (const float*)d_in[10];
    const float* ln2_g = (const float*)d_in[11];
    const float* ln2_b = (const float*)d_in[12];
    const float* lnf_g = (const float*)d_in[13];
    const float* lnf_b = (const float*)d_in[14];
    const float* W1    = (const float*)d_in[15];
    const float* b1    = (const float*)d_in[16];
    const float* W2    = (const float*)d_in[17];
    const float* b2    = (const float*)d_in[18];
    float* out = (float*)d_out;

    __half*   p_qln_h = (__half*)sym_addr(g_qln_h);
    float*    p_qln   = (float*)sym_addr(g_qln);
    __half*   p_vln_h = (__half*)sym_addr(g_vln_h);
    __half*   p_kln_h = (__half*)sym_addr(g_kln_h);
    __half*   p_Q     = (__half*)sym_addr(g_Q);
    __half*   p_K     = (__half*)sym_addr(g_K);
    __half*   p_V     = (__half*)sym_addr(g_V);
    uint32_t* p_Vp    = (uint32_t*)sym_addr(g_Vp);
    __half*   p_att   = (__half*)sym_addr(g_att);
    float*    p_x     = (float*)sym_addr(g_x);
    __half*   p_hh    = (__half*)sym_addr(g_hh);
    __half*   p_ff    = (__half*)sym_addr(g_ff);
    float*    p_mf    = (float*)sym_addr(g_maskf);
    uint32_t* p_Wq    = (uint32_t*)sym_addr(g_Wq);
    uint32_t* p_Wk    = (uint32_t*)sym_addr(g_Wk);
    uint32_t* p_Wv    = (uint32_t*)sym_addr(g_Wv);
    uint32_t* p_Wo    = (uint32_t*)sym_addr(g_Wo);
    uint32_t* p_W1    = (uint32_t*)sym_addr(g_W1);
    uint32_t* p_W2    = (uint32_t*)sym_addr(g_W2);

    const int GSM = GEMM_SMEM_WORDS * 4;     // 110592
    const int FSM = FLASH_SMEM_WORDS * 4;    // 55296
    cudaFuncSetAttribute(gemm_h<0,1>, cudaFuncAttributeMaxDynamicSharedMemorySize, GSM);
    cudaFuncSetAttribute(gemm_h<2,0>, cudaFuncAttributeMaxDynamicSharedMemorySize, GSM);
    cudaFuncSetAttribute(gemm_h<3,1>, cudaFuncAttributeMaxDynamicSharedMemorySize, GSM);
    cudaFuncSetAttribute(flash_kernel, cudaFuncAttributeMaxDynamicSharedMemorySize, FSM);

    // 0) mask addends + transposed weight packing (32n x 256k tiles)
    maskf_kernel<<<NTOK / 256, 256>>>(mask, p_mf);
    wpackT_kernel<<<dim3(EDIM/32, EDIM/256), 256>>>(Wq, p_Wq, EDIM, EDIM);
    wpackT_kernel<<<dim3(EDIM/32, EDIM/256), 256>>>(Wk, p_Wk, EDIM, EDIM);
    wpackT_kernel<<<dim3(EDIM/32, EDIM/256), 256>>>(Wv, p_Wv, EDIM, EDIM);
    wpackT_kernel<<<dim3(EDIM/32, EDIM/256), 256>>>(Wo, p_Wo, EDIM, EDIM);
    wpackT_kernel<<<dim3(FFDIM/32, EDIM/256), 256>>>(W1, p_W1, EDIM, FFDIM);
    wpackT_kernel<<<dim3(EDIM/32, FFDIM/256), 256>>>(W2, p_W2, FFDIM, EDIM);

    // 1) pre-norms (half outputs; raw fp32 LN1(q) for residual)
    ln_kernel<<<NTOK/8, 256>>>(query, (uint32_t*)p_qln_h, p_qln, ln1_g, ln1_b);
    ln_kernel<<<NTOK/8, 256>>>(value, (uint32_t*)p_vln_h, nullptr, ln2_g, ln2_b);
    ln_kernel<<<NTOK/8, 256>>>(key,   (uint32_t*)p_kln_h, nullptr, ln2_g, ln2_b);

    // 2) QKV projections (half out)
    dim3 gProj(EDIM / 128, NTOK / 128, 1);
    gemm_h<0,1><<<gProj, 256, GSM>>>(p_qln_h, p_Wq, p_Q, EDIM, EDIM, nullptr, nullptr);
    gemm_h<0,1><<<gProj, 256, GSM>>>(p_kln_h, p_Wk, p_K, EDIM, EDIM, nullptr, nullptr);
    gemm_h<0,1><<<gProj, 256, GSM>>>(p_vln_h, p_Wv, p_V, EDIM, EDIM, nullptr, nullptr);

    // 2b) pack V into token pairs for PV mma B-operand
    vpack_kernel<<<NTOK/2*EDIM/4/256, 256>>>((uint32_t*)p_V, p_Vp);

    // 3) fused attention (half out)
    dim3 gF(SEQ / 128, NHEAD, BATCH);
    flash_kernel<<<gF, 256, FSM>>>(p_Q, p_K, p_Vp, p_mf, (uint32_t*)p_att);

    // 4) x = att @ Wo + bo + LN1(q)_raw  (fp32 out)
    gemm_h<2,0><<<gProj, 256, GSM>>>(p_att, p_Wo, p_x, EDIM, EDIM, bo, p_qln);

    // 5) h = LN_f(x) (half out)
    ln_kernel<<<NTOK/8, 256>>>(p_x, (uint32_t*)p_hh, nullptr, lnf_g, lnf_b);

    // 6) ff = gelu(h @ W1 + b1) (half out)
    dim3 gF1(FFDIM / 128, NTOK / 128, 1);
    gemm_h<3,1><<<gF1, 256, GSM>>>(p_hh, p_W1, p_ff, EDIM, FFDIM, b1, nullptr);

    // 7) out = ff @ W2 + b2 + x (fp32 out)
    dim3 gF2(EDIM / 128, NTOK / 128, 1);
    gemm_h<2,0><<<gF2, 256, GSM>>>(p_ff, p_W2, out, FFDIM, EDIM, b2, p_x);
}